// round 3
// baseline (speedup 1.0000x reference)
#include <cuda_runtime.h>
#include <math.h>
#include <stdint.h>

#define SEQ   1024
#define BAT   4
#define DM    1024
#define NHEAD 16
#define HD    64
#define BNH   (BAT*NHEAD)   // 64
#define SKR   1088          // kr rows needed: p = S + j - i in [1, 1087] incl. masked tile corners
#define SCALE_F 0.125f      // 1/sqrt(64)
#define NEG_BIG -1.0e30f

// ---------------- scratch (static __device__, no allocations) ----------------
__device__ float g_q [BNH*SEQ*HD];
__device__ float g_k [BNH*SEQ*HD];
__device__ float g_v [BNH*SEQ*HD];
__device__ float g_kr[BNH*SKR*HD];
__device__ float g_ck [BNH*SEQ];     // rwb . k_j
__device__ float g_ckr[BNH*SKR];     // rrb . kr_p
__device__ float g_ef [BNH*SEQ*2];   // (q_i+rsb) . seg_embed[s]
__device__ float g_a  [BAT*SEQ];     // binary segment label per (b,i)
__device__ float g_sc [(size_t)BNH*SEQ*SEQ];  // scores -> probs (in-place)
__device__ float g_av [BNH*SEQ*HD];  // attention output per head
__device__ float g_ao [SEQ*BAT*DM];  // pre-layernorm output

// ---------------- projection GEMM: out[b,n,row,d] = sum_h in[row,b,h]*W[h,n,d]
// in: [nrows, BAT, DM] row-major. W: [DM, 1024] row-major. sel picks output buffer.
__global__ __launch_bounds__(256) void proj_kernel(const float* __restrict__ in,
                                                   const float* __restrict__ W,
                                                   int nrows, int sel)
{
    float* out = (sel == 0) ? g_q : (sel == 1) ? g_k : (sel == 2) ? g_v : g_kr;
    int b   = blockIdx.z;
    int row0 = blockIdx.x * 64;
    int c0   = blockIdx.y * 64;      // column block: n = c0>>6, d = c - c0
    __shared__ float As[16][65];
    __shared__ float Bs[16][65];
    int tid = threadIdx.x;
    int tx = tid & 15, ty = tid >> 4;
    float acc[4][4];
#pragma unroll
    for (int u = 0; u < 4; u++)
#pragma unroll
        for (int v = 0; v < 4; v++) acc[u][v] = 0.f;

    for (int k0 = 0; k0 < DM; k0 += 16) {
#pragma unroll
        for (int q = 0; q < 4; q++) {
            int e = tid + q * 256;
            int rr = e >> 4, kk = e & 15;
            As[kk][rr] = in[((size_t)(row0 + rr) * BAT + b) * DM + k0 + kk];
        }
#pragma unroll
        for (int q = 0; q < 4; q++) {
            int e = tid + q * 256;
            int cc = e & 63, kk = e >> 6;
            Bs[kk][cc] = W[(size_t)(k0 + kk) * 1024 + c0 + cc];
        }
        __syncthreads();
#pragma unroll
        for (int kk = 0; kk < 16; kk++) {
            float av[4], bv[4];
#pragma unroll
            for (int u = 0; u < 4; u++) av[u] = As[kk][ty * 4 + u];
#pragma unroll
            for (int v = 0; v < 4; v++) bv[v] = Bs[kk][tx * 4 + v];
#pragma unroll
            for (int u = 0; u < 4; u++)
#pragma unroll
                for (int v = 0; v < 4; v++) acc[u][v] += av[u] * bv[v];
        }
        __syncthreads();
    }
    int n = c0 >> 6;
    float* op = out + ((size_t)(b * NHEAD + n) * nrows) * HD;
#pragma unroll
    for (int u = 0; u < 4; u++)
#pragma unroll
        for (int v = 0; v < 4; v++)
            op[(size_t)(row0 + ty * 4 + u) * HD + tx * 4 + v] = acc[u][v];
}

// ---------------- segment labels: a[b][i] = seg_mat[0, i, b, 1] -----------------
__global__ void seg_kernel(const float* __restrict__ seg)
{
    int b = blockIdx.x;
    int i = threadIdx.x;   // 1024 threads
    g_a[b * SEQ + i] = seg[((size_t)i * BAT + b) * 2 + 1];
}

// ---------------- ck / ckr dot products (warp per row) --------------------------
__global__ __launch_bounds__(256) void ckdots_kernel(const float* __restrict__ rwb,
                                                     const float* __restrict__ rrb)
{
    int bn = blockIdx.y;
    int n  = bn & (NHEAD - 1);
    int wid  = threadIdx.x >> 5;
    int lane = threadIdx.x & 31;
    int j = blockIdx.x * 8 + wid;
    if (j >= SKR) return;
    // ckr
    {
        const float* kr = g_kr + ((size_t)bn * SKR + j) * HD;
        float s = rrb[n * HD + lane] * kr[lane] + rrb[n * HD + 32 + lane] * kr[32 + lane];
#pragma unroll
        for (int o = 16; o; o >>= 1) s += __shfl_down_sync(0xffffffffu, s, o);
        if (lane == 0) g_ckr[bn * SKR + j] = s;
    }
    if (j < SEQ) {
        const float* kp = g_k + ((size_t)bn * SEQ + j) * HD;
        float s = rwb[n * HD + lane] * kp[lane] + rwb[n * HD + 32 + lane] * kp[32 + lane];
#pragma unroll
        for (int o = 16; o; o >>= 1) s += __shfl_down_sync(0xffffffffu, s, o);
        if (lane == 0) g_ck[bn * SEQ + j] = s;
    }
}

// ---------------- ef[i,s] = (q_i + rsb) . seg_embed[s]  (warp per (bn,i)) ------
__global__ __launch_bounds__(256) void ef_kernel(const float* __restrict__ rsb,
                                                 const float* __restrict__ se)
{
    int bn = blockIdx.y;
    int n  = bn & (NHEAD - 1);
    int wid  = threadIdx.x >> 5;
    int lane = threadIdx.x & 31;
    int i = blockIdx.x * 8 + wid;    // gridDim.x = 128
    const float* qp = g_q + ((size_t)bn * SEQ + i) * HD;
    float q0 = qp[lane] + rsb[n * HD + lane];
    float q1 = qp[32 + lane] + rsb[n * HD + 32 + lane];
    float e0 = q0 * se[(0 * NHEAD + n) * HD + lane] + q1 * se[(0 * NHEAD + n) * HD + 32 + lane];
    float e1 = q0 * se[(1 * NHEAD + n) * HD + lane] + q1 * se[(1 * NHEAD + n) * HD + 32 + lane];
#pragma unroll
    for (int o = 16; o; o >>= 1) {
        e0 += __shfl_down_sync(0xffffffffu, e0, o);
        e1 += __shfl_down_sync(0xffffffffu, e1, o);
    }
    if (lane == 0) {
        g_ef[((size_t)bn * SEQ + i) * 2 + 0] = e0;
        g_ef[((size_t)bn * SEQ + i) * 2 + 1] = e1;
    }
}

// ---------------- fused score kernel: ac + banded bd + ef + mask ----------------
// Lower-triangle 64x64 tiles only. 256 threads, 4x4 microtiles.
__global__ __launch_bounds__(256) void score_kernel()
{
    int bn = blockIdx.z;
    int b  = bn >> 4;
    int t  = blockIdx.x;
    // triangular map t -> (it, jt), jt <= it
    int it = 0;
    while ((it + 1) * (it + 2) / 2 <= t) it++;
    int jt = t - it * (it + 1) / 2;
    int i0 = it * 64, j0 = jt * 64;
    int pmin = SEQ + j0 - i0 - 63;   // >= 1, pmin+126 <= 1087

    __shared__ float Qs[32][65];
    __shared__ float Ks[32][65];
    __shared__ float KRs[32][128];
    __shared__ float sck[64];
    __shared__ float sckr[127];
    __shared__ float sef[128];
    __shared__ float sai[64];
    __shared__ float saj[64];

    int tid = threadIdx.x;
    int tx = tid & 15, ty = tid >> 4;

    if (tid < 64)  sck[tid]  = g_ck[(size_t)bn * SEQ + j0 + tid];
    if (tid < 127) sckr[tid] = g_ckr[(size_t)bn * SKR + pmin + tid];
    if (tid < 128) sef[tid]  = g_ef[((size_t)bn * SEQ + i0) * 2 + tid];
    if (tid >= 128 && tid < 192) sai[tid - 128] = g_a[b * SEQ + i0 + (tid - 128)];
    if (tid >= 192) saj[tid - 192] = g_a[b * SEQ + j0 + (tid - 192)];

    float acc[4][4];
#pragma unroll
    for (int u = 0; u < 4; u++)
#pragma unroll
        for (int v = 0; v < 4; v++) acc[u][v] = 0.f;

    int cbase = (tx - ty) * 4 + 63;

    for (int kb = 0; kb < HD; kb += 32) {
#pragma unroll
        for (int q = 0; q < 8; q++) {
            int e = tid + q * 256;
            int rr = e >> 5, kk = e & 31;
            Qs[kk][rr] = g_q[((size_t)bn * SEQ + i0 + rr) * HD + kb + kk];
            Ks[kk][rr] = g_k[((size_t)bn * SEQ + j0 + rr) * HD + kb + kk];
        }
#pragma unroll
        for (int q = 0; q < 16; q++) {
            int e = tid + q * 256;
            if (e < 127 * 32) {
                int l = e >> 5, kk = e & 31;
                KRs[kk][l] = g_kr[((size_t)bn * SKR + pmin + l) * HD + kb + kk];
            }
        }
        __syncthreads();
#pragma unroll
        for (int kk = 0; kk < 32; kk++) {
            float qv[4], kv[4], dv[7];
#pragma unroll
            for (int u = 0; u < 4; u++) qv[u] = Qs[kk][ty * 4 + u];
#pragma unroll
            for (int v = 0; v < 4; v++) kv[v] = Ks[kk][tx * 4 + v];
#pragma unroll
            for (int w = 0; w < 7; w++) dv[w] = KRs[kk][cbase - 3 + w];
#pragma unroll
            for (int u = 0; u < 4; u++)
#pragma unroll
                for (int v = 0; v < 4; v++)
                    acc[u][v] += qv[u] * (kv[v] + dv[v - u + 3]);
        }
        __syncthreads();
    }

    size_t base = (size_t)bn * SEQ * SEQ;
#pragma unroll
    for (int u = 0; u < 4; u++) {
        int ii = ty * 4 + u;
        int i  = i0 + ii;
        float ai  = sai[ii];
        float ef0 = sef[ii * 2 + 0];
        float ef1 = sef[ii * 2 + 1];
#pragma unroll
        for (int v = 0; v < 4; v++) {
            int jj = tx * 4 + v;
            int j  = j0 + jj;
            float val;
            if (j > i) {
                val = NEG_BIG;
            } else {
                float efv = (ai != saj[jj]) ? ef1 : ef0;
                val = (acc[u][v] + sck[jj] + sckr[jj - ii + 63] + efv) * SCALE_F;
            }
            g_sc[base + (size_t)i * SEQ + j] = val;
        }
    }
}

// ---------------- softmax per row (causal), in-place, zeros above diagonal -----
__global__ __launch_bounds__(256) void softmax_kernel()
{
    int i  = blockIdx.x;
    int bn = blockIdx.y;
    size_t base = ((size_t)bn * SEQ + i) * SEQ;
    int tid = threadIdx.x;
    int len = i + 1;
    float v[4];
    float m = -3.4e38f;
#pragma unroll
    for (int k = 0; k < 4; k++) {
        int j = tid + k * 256;
        v[k] = (j < len) ? g_sc[base + j] : -3.4e38f;
        m = fmaxf(m, v[k]);
    }
    __shared__ float red[256];
    red[tid] = m; __syncthreads();
    for (int s = 128; s > 0; s >>= 1) { if (tid < s) red[tid] = fmaxf(red[tid], red[tid + s]); __syncthreads(); }
    m = red[0]; __syncthreads();
    float sum = 0.f;
    float e[4];
#pragma unroll
    for (int k = 0; k < 4; k++) {
        int j = tid + k * 256;
        e[k] = (j < len) ? expf(v[k] - m) : 0.f;
        sum += e[k];
    }
    red[tid] = sum; __syncthreads();
    for (int s = 128; s > 0; s >>= 1) { if (tid < s) red[tid] += red[tid + s]; __syncthreads(); }
    float inv = 1.f / red[0];
#pragma unroll
    for (int k = 0; k < 4; k++) {
        int j = tid + k * 256;
        g_sc[base + j] = e[k] * inv;
    }
}

// ---------------- PV GEMM: av[bn,i,d] = sum_j P[i,j] * v[bn,j,d] ----------------
__global__ __launch_bounds__(256) void pv_kernel()
{
    int bn = blockIdx.z;
    int i0 = blockIdx.x * 64;
    __shared__ float As[16][65];
    __shared__ float Bs[16][65];
    int tid = threadIdx.x;
    int tx = tid & 15, ty = tid >> 4;
    float acc[4][4];
#pragma unroll
    for (int u = 0; u < 4; u++)
#pragma unroll
        for (int v = 0; v < 4; v++) acc[u][v] = 0.f;

    int kmax = i0 + 64;   // probs are zero beyond the diagonal
    for (int k0 = 0; k0 < kmax; k0 += 16) {
#pragma unroll
        for (int q = 0; q < 4; q++) {
            int e = tid + q * 256;
            int rr = e >> 4, kk = e & 15;
            As[kk][rr] = g_sc[((size_t)bn * SEQ + i0 + rr) * SEQ + k0 + kk];
        }
#pragma unroll
        for (int q = 0; q < 4; q++) {
            int e = tid + q * 256;
            int cc = e & 63, kk = e >> 6;
            Bs[kk][cc] = g_v[((size_t)bn * SEQ + k0 + kk) * HD + cc];
        }
        __syncthreads();
#pragma unroll
        for (int kk = 0; kk < 16; kk++) {
            float av[4], bv[4];
#pragma unroll
            for (int u = 0; u < 4; u++) av[u] = As[kk][ty * 4 + u];
#pragma unroll
            for (int v = 0; v < 4; v++) bv[v] = Bs[kk][tx * 4 + v];
#pragma unroll
            for (int u = 0; u < 4; u++)
#pragma unroll
                for (int v = 0; v < 4; v++) acc[u][v] += av[u] * bv[v];
        }
        __syncthreads();
    }
#pragma unroll
    for (int u = 0; u < 4; u++)
#pragma unroll
        for (int v = 0; v < 4; v++)
            g_av[((size_t)bn * SEQ + i0 + ty * 4 + u) * HD + tx * 4 + v] = acc[u][v];
}

// ---------------- Wo GEMM + residual: ao[row, h'] = sum_c av.Wo + h -------------
// rows m = i*BAT + b (matches h layout [i,b,:]); c = n*64 + d
__global__ __launch_bounds__(256) void out_kernel(const float* __restrict__ Wo,
                                                  const float* __restrict__ hin)
{
    int row0 = blockIdx.x * 64;
    int c0   = blockIdx.y * 64;
    __shared__ float As[16][65];
    __shared__ float Bs[16][65];
    int tid = threadIdx.x;
    int tx = tid & 15, ty = tid >> 4;
    float acc[4][4];
#pragma unroll
    for (int u = 0; u < 4; u++)
#pragma unroll
        for (int v = 0; v < 4; v++) acc[u][v] = 0.f;

    for (int k0 = 0; k0 < DM; k0 += 16) {
        int n = k0 >> 6;
        int dbase = k0 & 63;
#pragma unroll
        for (int q = 0; q < 4; q++) {
            int e = tid + q * 256;
            int rr = e >> 4, kk = e & 15;
            int row = row0 + rr;
            int b = row & 3, i = row >> 2;
            As[kk][rr] = g_av[((size_t)(b * NHEAD + n) * SEQ + i) * HD + dbase + kk];
        }
#pragma unroll
        for (int q = 0; q < 4; q++) {
            int e = tid + q * 256;
            int kk = e & 15, cc = e >> 4;
            Bs[kk][cc] = Wo[(size_t)(c0 + cc) * 1024 + k0 + kk];
        }
        __syncthreads();
#pragma unroll
        for (int kk = 0; kk < 16; kk++) {
            float av[4], bv[4];
#pragma unroll
            for (int u = 0; u < 4; u++) av[u] = As[kk][ty * 4 + u];
#pragma unroll
            for (int v = 0; v < 4; v++) bv[v] = Bs[kk][tx * 4 + v];
#pragma unroll
            for (int u = 0; u < 4; u++)
#pragma unroll
                for (int v = 0; v < 4; v++) acc[u][v] += av[u] * bv[v];
        }
        __syncthreads();
    }
#pragma unroll
    for (int u = 0; u < 4; u++) {
        int row = row0 + ty * 4 + u;
#pragma unroll
        for (int v = 0; v < 4; v++) {
            int c = c0 + tx * 4 + v;
            g_ao[(size_t)row * DM + c] = acc[u][v] + hin[(size_t)row * DM + c];
        }
    }
}

// ---------------- LayerNorm over D --------------------------------------------
__global__ __launch_bounds__(256) void ln_kernel(const float* __restrict__ lns,
                                                 const float* __restrict__ lnb,
                                                 float* __restrict__ out)
{
    int row = blockIdx.x;
    int tid = threadIdx.x;
    const float* x = g_ao + (size_t)row * DM;
    float v[4];
    float s = 0.f;
#pragma unroll
    for (int k = 0; k < 4; k++) { v[k] = x[tid + k * 256]; s += v[k]; }
    __shared__ float red[256];
    red[tid] = s; __syncthreads();
    for (int t = 128; t > 0; t >>= 1) { if (tid < t) red[tid] += red[tid + t]; __syncthreads(); }
    float mu = red[0] * (1.f / DM);
    __syncthreads();
    float s2 = 0.f;
#pragma unroll
    for (int k = 0; k < 4; k++) { float d = v[k] - mu; s2 += d * d; }
    red[tid] = s2; __syncthreads();
    for (int t = 128; t > 0; t >>= 1) { if (tid < t) red[tid] += red[tid + t]; __syncthreads(); }
    float var = red[0] * (1.f / DM);
    float inv = rsqrtf(var + 1e-12f);
#pragma unroll
    for (int k = 0; k < 4; k++) {
        int j = tid + k * 256;
        out[(size_t)row * DM + j] = (v[k] - mu) * inv * lns[j] + lnb[j];
    }
}

// ---------------- launch --------------------------------------------------------
extern "C" void kernel_launch(void* const* d_in, const int* in_sizes, int n_in,
                              void* d_out, int out_size)
{
    const float* h   = (const float*)d_in[0];
    const float* r   = (const float*)d_in[1];
    const float* seg = (const float*)d_in[2];
    // d_in[3] = attn_mask (pure causal; reconstructed from indices)
    const float* Wq  = (const float*)d_in[4];
    const float* Wk  = (const float*)d_in[5];
    const float* Wv  = (const float*)d_in[6];
    const float* Wo  = (const float*)d_in[7];
    const float* Wr  = (const float*)d_in[8];
    const float* rwb = (const float*)d_in[9];
    const float* rrb = (const float*)d_in[10];
    const float* rsb = (const float*)d_in[11];
    const float* se  = (const float*)d_in[12];
    const float* lns = (const float*)d_in[13];
    const float* lnb = (const float*)d_in[14];
    float* out = (float*)d_out;

    // projections
    proj_kernel<<<dim3(SEQ/64, 16, BAT), 256>>>(h, Wq, SEQ, 0);
    proj_kernel<<<dim3(SEQ/64, 16, BAT), 256>>>(h, Wk, SEQ, 1);
    proj_kernel<<<dim3(SEQ/64, 16, BAT), 256>>>(h, Wv, SEQ, 2);
    proj_kernel<<<dim3(SKR/64, 16, BAT), 256>>>(r, Wr, SKR, 3);

    // small precomputes
    seg_kernel<<<BAT, SEQ>>>(seg);
    ckdots_kernel<<<dim3((SKR + 7) / 8, BNH), 256>>>(rwb, rrb);
    ef_kernel<<<dim3(SEQ / 8, BNH), 256>>>(rsb, se);

    // fused scores (lower triangle tiles), softmax, PV
    score_kernel<<<dim3(136, 1, BNH), 256>>>();
    softmax_kernel<<<dim3(SEQ, BNH), 256>>>();
    pv_kernel<<<dim3(SEQ/64, 1, BNH), 256>>>();

    // output projection + residual, then layernorm
    out_kernel<<<dim3((SEQ*BAT)/64, DM/64), 256>>>(Wo, h);
    ln_kernel<<<SEQ*BAT, 256>>>(lns, lnb, out);
}

// round 4
// speedup vs baseline: 1.4511x; 1.4511x over previous
#include <cuda_runtime.h>
#include <math.h>
#include <stdint.h>

#define SEQ   1024
#define BAT   4
#define DM    1024
#define NHEAD 16
#define HD    64
#define BNH   (BAT*NHEAD)   // 64
#define SKR   1152          // kr rows: p = S + j - i reaches 1151 on 128-wide diagonal tiles
#define SCALE_F 0.125f
#define NEG_BIG -1.0e30f

// ---------------- scratch ----------------
__device__ float g_q [BNH*SEQ*HD];
__device__ float g_k [BNH*SEQ*HD];
__device__ float g_v [BNH*SEQ*HD];
__device__ float g_kr[BNH*SKR*HD];
__device__ float g_ck [BNH*SEQ];
__device__ float g_ckr[BNH*SKR];
__device__ float g_ef [BNH*SEQ*2];
__device__ float g_a  [BAT*SEQ];
__device__ float g_sc [(size_t)BNH*SEQ*SEQ];
__device__ float g_av [BNH*SEQ*HD];
__device__ float g_ao [SEQ*BAT*DM];

// ---------------- projection GEMM: 128x128 tile, 8x8 microtile ----------------
// out[b,n,row,d] = sum_k in[row,b,k] * W[k, n*64+d]
__global__ __launch_bounds__(256) void proj_kernel(const float* __restrict__ in,
                                                   const float* __restrict__ W,
                                                   int nrows, int sel)
{
    float* out = (sel == 0) ? g_q : (sel == 1) ? g_k : (sel == 2) ? g_v : g_kr;
    int b    = blockIdx.z;
    int row0 = blockIdx.x * 128;
    int c0   = blockIdx.y * 128;
    __shared__ __align__(16) float As[16][132];
    __shared__ __align__(16) float Bs[16][132];
    int tid = threadIdx.x;
    int tx = tid & 15, ty = tid >> 4;

    float acc[8][8];
#pragma unroll
    for (int u = 0; u < 8; u++)
#pragma unroll
        for (int v = 0; v < 8; v++) acc[u][v] = 0.f;

    for (int k0 = 0; k0 < DM; k0 += 16) {
#pragma unroll
        for (int q = 0; q < 2; q++) {            // A: 128 rows x 16 k, transposed store
            int f = tid * 2 + q;
            int rr = f >> 2, kk4 = f & 3;
            const float4 t = *(const float4*)(in + ((size_t)(row0 + rr) * BAT + b) * DM + k0 + kk4 * 4);
            As[kk4 * 4 + 0][rr] = t.x;
            As[kk4 * 4 + 1][rr] = t.y;
            As[kk4 * 4 + 2][rr] = t.z;
            As[kk4 * 4 + 3][rr] = t.w;
        }
#pragma unroll
        for (int q = 0; q < 2; q++) {            // B: 16 k x 128 cols, direct store
            int f = tid * 2 + q;
            int kk = f >> 5, cc4 = f & 31;
            *(float4*)&Bs[kk][cc4 * 4] = *(const float4*)(W + (size_t)(k0 + kk) * 1024 + c0 + cc4 * 4);
        }
        __syncthreads();
#pragma unroll
        for (int kk = 0; kk < 16; kk++) {
            float4 a0 = *(const float4*)&As[kk][ty * 8];
            float4 a1 = *(const float4*)&As[kk][ty * 8 + 4];
            float4 b0 = *(const float4*)&Bs[kk][tx * 8];
            float4 b1 = *(const float4*)&Bs[kk][tx * 8 + 4];
            float av[8] = {a0.x, a0.y, a0.z, a0.w, a1.x, a1.y, a1.z, a1.w};
            float bv[8] = {b0.x, b0.y, b0.z, b0.w, b1.x, b1.y, b1.z, b1.w};
#pragma unroll
            for (int u = 0; u < 8; u++)
#pragma unroll
                for (int v = 0; v < 8; v++) acc[u][v] += av[u] * bv[v];
        }
        __syncthreads();
    }
    int cb = c0 + tx * 8;
    int n  = cb >> 6;
    int d0 = cb & 63;
    float* op = out + ((size_t)(b * NHEAD + n) * nrows + row0 + ty * 8) * HD + d0;
#pragma unroll
    for (int u = 0; u < 8; u++) {
        float4 s0 = make_float4(acc[u][0], acc[u][1], acc[u][2], acc[u][3]);
        float4 s1 = make_float4(acc[u][4], acc[u][5], acc[u][6], acc[u][7]);
        *(float4*)(op + (size_t)u * HD)     = s0;
        *(float4*)(op + (size_t)u * HD + 4) = s1;
    }
}

// ---------------- segment labels -----------------
__global__ void seg_kernel(const float* __restrict__ seg)
{
    int b = blockIdx.x;
    int i = threadIdx.x;
    g_a[b * SEQ + i] = seg[((size_t)i * BAT + b) * 2 + 1];
}

// ---------------- ck / ckr dot products --------------------------
__global__ __launch_bounds__(256) void ckdots_kernel(const float* __restrict__ rwb,
                                                     const float* __restrict__ rrb)
{
    int bn = blockIdx.y;
    int n  = bn & (NHEAD - 1);
    int wid  = threadIdx.x >> 5;
    int lane = threadIdx.x & 31;
    int j = blockIdx.x * 8 + wid;
    if (j >= SKR) return;
    {
        const float* kr = g_kr + ((size_t)bn * SKR + j) * HD;
        float s = rrb[n * HD + lane] * kr[lane] + rrb[n * HD + 32 + lane] * kr[32 + lane];
#pragma unroll
        for (int o = 16; o; o >>= 1) s += __shfl_down_sync(0xffffffffu, s, o);
        if (lane == 0) g_ckr[bn * SKR + j] = s;
    }
    if (j < SEQ) {
        const float* kp = g_k + ((size_t)bn * SEQ + j) * HD;
        float s = rwb[n * HD + lane] * kp[lane] + rwb[n * HD + 32 + lane] * kp[32 + lane];
#pragma unroll
        for (int o = 16; o; o >>= 1) s += __shfl_down_sync(0xffffffffu, s, o);
        if (lane == 0) g_ck[bn * SEQ + j] = s;
    }
}

// ---------------- ef[i,s] = (q_i + rsb) . seg_embed[s] ------
__global__ __launch_bounds__(256) void ef_kernel(const float* __restrict__ rsb,
                                                 const float* __restrict__ se)
{
    int bn = blockIdx.y;
    int n  = bn & (NHEAD - 1);
    int wid  = threadIdx.x >> 5;
    int lane = threadIdx.x & 31;
    int i = blockIdx.x * 8 + wid;
    const float* qp = g_q + ((size_t)bn * SEQ + i) * HD;
    float q0 = qp[lane] + rsb[n * HD + lane];
    float q1 = qp[32 + lane] + rsb[n * HD + 32 + lane];
    float e0 = q0 * se[(0 * NHEAD + n) * HD + lane] + q1 * se[(0 * NHEAD + n) * HD + 32 + lane];
    float e1 = q0 * se[(1 * NHEAD + n) * HD + lane] + q1 * se[(1 * NHEAD + n) * HD + 32 + lane];
#pragma unroll
    for (int o = 16; o; o >>= 1) {
        e0 += __shfl_down_sync(0xffffffffu, e0, o);
        e1 += __shfl_down_sync(0xffffffffu, e1, o);
    }
    if (lane == 0) {
        g_ef[((size_t)bn * SEQ + i) * 2 + 0] = e0;
        g_ef[((size_t)bn * SEQ + i) * 2 + 1] = e1;
    }
}

// ---------------- fused score kernel: 128x128 tile, 8x8 microtile ----------------
__global__ __launch_bounds__(256) void score_kernel()
{
    int bn = blockIdx.z;
    int b  = bn >> 4;
    int t  = blockIdx.x;
    int it = 0;
    while ((it + 1) * (it + 2) / 2 <= t) it++;
    int jt = t - it * (it + 1) / 2;
    int i0 = it * 128, j0 = jt * 128;
    int pmin = SEQ + j0 - i0 - 127;          // >= 1; pmin+254 <= 1151 < SKR

    __shared__ __align__(16) float Qs[16][132];
    __shared__ __align__(16) float Ks[16][132];
    __shared__ __align__(16) float KRs[16][260];
    __shared__ float sck[128];
    __shared__ float sckr[256];
    __shared__ float sef[256];
    __shared__ float sai[128];
    __shared__ float saj[128];

    int tid = threadIdx.x;
    int tx = tid & 15, ty = tid >> 4;

    if (tid < 128) {
        sck[tid] = g_ck[(size_t)bn * SEQ + j0 + tid];
        sai[tid] = g_a[b * SEQ + i0 + tid];
        saj[tid] = g_a[b * SEQ + j0 + tid];
    } else {
        int x = tid - 128;
        sef[x]       = g_ef[((size_t)bn * SEQ + i0) * 2 + x];
        sef[x + 128] = g_ef[((size_t)bn * SEQ + i0) * 2 + x + 128];
    }
    if (tid < 255) sckr[tid] = g_ckr[(size_t)bn * SKR + pmin + tid];

    float acc[8][8];
#pragma unroll
    for (int u = 0; u < 8; u++)
#pragma unroll
        for (int v = 0; v < 8; v++) acc[u][v] = 0.f;

    int dbase = (tx - ty) * 8 + 120;         // KRs column base for this thread's 15 diagonals

    for (int kb = 0; kb < HD; kb += 16) {
#pragma unroll
        for (int q = 0; q < 2; q++) {
            int f = tid * 2 + q;
            int rr = f >> 2, kk4 = f & 3;
            const float4 tq = *(const float4*)(g_q + ((size_t)bn * SEQ + i0 + rr) * HD + kb + kk4 * 4);
            Qs[kk4 * 4 + 0][rr] = tq.x; Qs[kk4 * 4 + 1][rr] = tq.y;
            Qs[kk4 * 4 + 2][rr] = tq.z; Qs[kk4 * 4 + 3][rr] = tq.w;
            const float4 tk = *(const float4*)(g_k + ((size_t)bn * SEQ + j0 + rr) * HD + kb + kk4 * 4);
            Ks[kk4 * 4 + 0][rr] = tk.x; Ks[kk4 * 4 + 1][rr] = tk.y;
            Ks[kk4 * 4 + 2][rr] = tk.z; Ks[kk4 * 4 + 3][rr] = tk.w;
        }
        // KRs: 256 band rows x 16 k (row 255 zero-padded); thread tid owns row tid
#pragma unroll
        for (int q = 0; q < 4; q++) {
            float4 tr = make_float4(0.f, 0.f, 0.f, 0.f);
            if (tid < 255)
                tr = *(const float4*)(g_kr + ((size_t)bn * SKR + pmin + tid) * HD + kb + q * 4);
            KRs[q * 4 + 0][tid] = tr.x; KRs[q * 4 + 1][tid] = tr.y;
            KRs[q * 4 + 2][tid] = tr.z; KRs[q * 4 + 3][tid] = tr.w;
        }
        __syncthreads();
#pragma unroll
        for (int kk = 0; kk < 16; kk++) {
            float4 a0 = *(const float4*)&Qs[kk][ty * 8];
            float4 a1 = *(const float4*)&Qs[kk][ty * 8 + 4];
            float4 b0 = *(const float4*)&Ks[kk][tx * 8];
            float4 b1 = *(const float4*)&Ks[kk][tx * 8 + 4];
            float4 d0 = *(const float4*)&KRs[kk][dbase];
            float4 d1 = *(const float4*)&KRs[kk][dbase + 4];
            float4 d2 = *(const float4*)&KRs[kk][dbase + 8];
            float4 d3 = *(const float4*)&KRs[kk][dbase + 12];
            float qv[8] = {a0.x, a0.y, a0.z, a0.w, a1.x, a1.y, a1.z, a1.w};
            float kv[8] = {b0.x, b0.y, b0.z, b0.w, b1.x, b1.y, b1.z, b1.w};
            float dv[16] = {d0.x, d0.y, d0.z, d0.w, d1.x, d1.y, d1.z, d1.w,
                            d2.x, d2.y, d2.z, d2.w, d3.x, d3.y, d3.z, d3.w};
#pragma unroll
            for (int u = 0; u < 8; u++)
#pragma unroll
                for (int v = 0; v < 8; v++)
                    acc[u][v] += qv[u] * (kv[v] + dv[v - u + 7]);
        }
        __syncthreads();
    }

    size_t base = (size_t)bn * SEQ * SEQ;
    int dbase7 = (tx - ty) * 8 + 127;
#pragma unroll
    for (int u = 0; u < 8; u++) {
        int ii = ty * 8 + u;
        int i  = i0 + ii;
        float ai  = sai[ii];
        float ef0 = sef[ii * 2 + 0];
        float ef1 = sef[ii * 2 + 1];
        float row[8];
#pragma unroll
        for (int v = 0; v < 8; v++) {
            int jj = tx * 8 + v;
            int j  = j0 + jj;
            if (j > i) {
                row[v] = NEG_BIG;
            } else {
                float efv = (ai != saj[jj]) ? ef1 : ef0;
                row[v] = (acc[u][v] + sck[jj] + sckr[dbase7 + v - u] + efv) * SCALE_F;
            }
        }
        float* op = &g_sc[base + (size_t)i * SEQ + j0 + tx * 8];
        *(float4*)(op)     = make_float4(row[0], row[1], row[2], row[3]);
        *(float4*)(op + 4) = make_float4(row[4], row[5], row[6], row[7]);
    }
}

// ---------------- softmax per row (causal) -----
__global__ __launch_bounds__(256) void softmax_kernel()
{
    int i  = blockIdx.x;
    int bn = blockIdx.y;
    size_t base = ((size_t)bn * SEQ + i) * SEQ;
    int tid = threadIdx.x;
    int len = i + 1;
    float v[4];
    float m = -3.4e38f;
#pragma unroll
    for (int k = 0; k < 4; k++) {
        int j = tid + k * 256;
        v[k] = (j < len) ? g_sc[base + j] : -3.4e38f;
        m = fmaxf(m, v[k]);
    }
    __shared__ float red[256];
    red[tid] = m; __syncthreads();
    for (int s = 128; s > 0; s >>= 1) { if (tid < s) red[tid] = fmaxf(red[tid], red[tid + s]); __syncthreads(); }
    m = red[0]; __syncthreads();
    float sum = 0.f;
    float e[4];
#pragma unroll
    for (int k = 0; k < 4; k++) {
        int j = tid + k * 256;
        e[k] = (j < len) ? expf(v[k] - m) : 0.f;
        sum += e[k];
    }
    red[tid] = sum; __syncthreads();
    for (int s = 128; s > 0; s >>= 1) { if (tid < s) red[tid] += red[tid + s]; __syncthreads(); }
    float inv = 1.f / red[0];
#pragma unroll
    for (int k = 0; k < 4; k++) {
        int j = tid + k * 256;
        g_sc[base + j] = e[k] * inv;
    }
}

// ---------------- PV GEMM: 128x64 tile, 8x4 microtile ----------------
__global__ __launch_bounds__(256) void pv_kernel()
{
    int bn = blockIdx.z;
    int i0 = blockIdx.x * 128;
    __shared__ __align__(16) float As[16][132];
    __shared__ __align__(16) float Bs[16][68];
    int tid = threadIdx.x;
    int tx = tid & 15, ty = tid >> 4;
    float acc[8][4];
#pragma unroll
    for (int u = 0; u < 8; u++)
#pragma unroll
        for (int v = 0; v < 4; v++) acc[u][v] = 0.f;

    int kmax = i0 + 128;
    for (int k0 = 0; k0 < kmax; k0 += 16) {
#pragma unroll
        for (int q = 0; q < 2; q++) {
            int f = tid * 2 + q;
            int rr = f >> 2, kk4 = f & 3;
            const float4 t = *(const float4*)(g_sc + ((size_t)bn * SEQ + i0 + rr) * SEQ + k0 + kk4 * 4);
            As[kk4 * 4 + 0][rr] = t.x; As[kk4 * 4 + 1][rr] = t.y;
            As[kk4 * 4 + 2][rr] = t.z; As[kk4 * 4 + 3][rr] = t.w;
        }
        {
            int kk = tid >> 4, cc4 = tid & 15;
            *(float4*)&Bs[kk][cc4 * 4] = *(const float4*)(g_v + ((size_t)bn * SEQ + k0 + kk) * HD + cc4 * 4);
        }
        __syncthreads();
#pragma unroll
        for (int kk = 0; kk < 16; kk++) {
            float4 a0 = *(const float4*)&As[kk][ty * 8];
            float4 a1 = *(const float4*)&As[kk][ty * 8 + 4];
            float4 b0 = *(const float4*)&Bs[kk][tx * 4];
            float av[8] = {a0.x, a0.y, a0.z, a0.w, a1.x, a1.y, a1.z, a1.w};
            float bv[4] = {b0.x, b0.y, b0.z, b0.w};
#pragma unroll
            for (int u = 0; u < 8; u++)
#pragma unroll
                for (int v = 0; v < 4; v++) acc[u][v] += av[u] * bv[v];
        }
        __syncthreads();
    }
#pragma unroll
    for (int u = 0; u < 8; u++) {
        float* op = g_av + ((size_t)bn * SEQ + i0 + ty * 8 + u) * HD + tx * 4;
        *(float4*)op = make_float4(acc[u][0], acc[u][1], acc[u][2], acc[u][3]);
    }
}

// ---------------- Wo GEMM + residual: 128x128, 8x8 ----------------
__global__ __launch_bounds__(256) void out_kernel(const float* __restrict__ Wo,
                                                  const float* __restrict__ hin)
{
    int row0 = blockIdx.x * 128;
    int c0   = blockIdx.y * 128;
    __shared__ __align__(16) float As[16][132];
    __shared__ __align__(16) float Bs[16][132];
    int tid = threadIdx.x;
    int tx = tid & 15, ty = tid >> 4;
    float acc[8][8];
#pragma unroll
    for (int u = 0; u < 8; u++)
#pragma unroll
        for (int v = 0; v < 8; v++) acc[u][v] = 0.f;

    for (int k0 = 0; k0 < DM; k0 += 16) {
#pragma unroll
        for (int q = 0; q < 2; q++) {            // A from g_av (row = i*BAT+b)
            int f = tid * 2 + q;
            int rr = f >> 2, kk4 = f & 3;
            int row = row0 + rr;
            int bb = row & 3, ii = row >> 2;
            int k = k0 + kk4 * 4;
            int n = k >> 6, d = k & 63;
            const float4 t = *(const float4*)(g_av + ((size_t)(bb * NHEAD + n) * SEQ + ii) * HD + d);
            As[kk4 * 4 + 0][rr] = t.x; As[kk4 * 4 + 1][rr] = t.y;
            As[kk4 * 4 + 2][rr] = t.z; As[kk4 * 4 + 3][rr] = t.w;
        }
#pragma unroll
        for (int q = 0; q < 2; q++) {            // B = Wo[c][k], contiguous in k -> transpose
            int f = tid * 2 + q;
            int cc = f >> 2, kk4 = f & 3;
            const float4 t = *(const float4*)(Wo + (size_t)(c0 + cc) * 1024 + k0 + kk4 * 4);
            Bs[kk4 * 4 + 0][cc] = t.x; Bs[kk4 * 4 + 1][cc] = t.y;
            Bs[kk4 * 4 + 2][cc] = t.z; Bs[kk4 * 4 + 3][cc] = t.w;
        }
        __syncthreads();
#pragma unroll
        for (int kk = 0; kk < 16; kk++) {
            float4 a0 = *(const float4*)&As[kk][ty * 8];
            float4 a1 = *(const float4*)&As[kk][ty * 8 + 4];
            float4 b0 = *(const float4*)&Bs[kk][tx * 8];
            float4 b1 = *(const float4*)&Bs[kk][tx * 8 + 4];
            float av[8] = {a0.x, a0.y, a0.z, a0.w, a1.x, a1.y, a1.z, a1.w};
            float bv[8] = {b0.x, b0.y, b0.z, b0.w, b1.x, b1.y, b1.z, b1.w};
#pragma unroll
            for (int u = 0; u < 8; u++)
#pragma unroll
                for (int v = 0; v < 8; v++) acc[u][v] += av[u] * bv[v];
        }
        __syncthreads();
    }
#pragma unroll
    for (int u = 0; u < 8; u++) {
        int row = row0 + ty * 8 + u;
        const float4 h0 = *(const float4*)(hin + (size_t)row * DM + c0 + tx * 8);
        const float4 h1 = *(const float4*)(hin + (size_t)row * DM + c0 + tx * 8 + 4);
        float4 s0 = make_float4(acc[u][0] + h0.x, acc[u][1] + h0.y, acc[u][2] + h0.z, acc[u][3] + h0.w);
        float4 s1 = make_float4(acc[u][4] + h1.x, acc[u][5] + h1.y, acc[u][6] + h1.z, acc[u][7] + h1.w);
        *(float4*)(g_ao + (size_t)row * DM + c0 + tx * 8)     = s0;
        *(float4*)(g_ao + (size_t)row * DM + c0 + tx * 8 + 4) = s1;
    }
}

// ---------------- LayerNorm --------------------------------------------
__global__ __launch_bounds__(256) void ln_kernel(const float* __restrict__ lns,
                                                 const float* __restrict__ lnb,
                                                 float* __restrict__ out)
{
    int row = blockIdx.x;
    int tid = threadIdx.x;
    const float* x = g_ao + (size_t)row * DM;
    float v[4];
    float s = 0.f;
#pragma unroll
    for (int k = 0; k < 4; k++) { v[k] = x[tid + k * 256]; s += v[k]; }
    __shared__ float red[256];
    red[tid] = s; __syncthreads();
    for (int t = 128; t > 0; t >>= 1) { if (tid < t) red[tid] += red[tid + t]; __syncthreads(); }
    float mu = red[0] * (1.f / DM);
    __syncthreads();
    float s2 = 0.f;
#pragma unroll
    for (int k = 0; k < 4; k++) { float d = v[k] - mu; s2 += d * d; }
    red[tid] = s2; __syncthreads();
    for (int t = 128; t > 0; t >>= 1) { if (tid < t) red[tid] += red[tid + t]; __syncthreads(); }
    float var = red[0] * (1.f / DM);
    float inv = rsqrtf(var + 1e-12f);
#pragma unroll
    for (int k = 0; k < 4; k++) {
        int j = tid + k * 256;
        out[(size_t)row * DM + j] = (v[k] - mu) * inv * lns[j] + lnb[j];
    }
}

// ---------------- launch --------------------------------------------------------
extern "C" void kernel_launch(void* const* d_in, const int* in_sizes, int n_in,
                              void* d_out, int out_size)
{
    const float* h   = (const float*)d_in[0];
    const float* r   = (const float*)d_in[1];
    const float* seg = (const float*)d_in[2];
    const float* Wq  = (const float*)d_in[4];
    const float* Wk  = (const float*)d_in[5];
    const float* Wv  = (const float*)d_in[6];
    const float* Wo  = (const float*)d_in[7];
    const float* Wr  = (const float*)d_in[8];
    const float* rwb = (const float*)d_in[9];
    const float* rrb = (const float*)d_in[10];
    const float* rsb = (const float*)d_in[11];
    const float* se  = (const float*)d_in[12];
    const float* lns = (const float*)d_in[13];
    const float* lnb = (const float*)d_in[14];
    float* out = (float*)d_out;

    proj_kernel<<<dim3(SEQ/128, DM/128, BAT), 256>>>(h, Wq, SEQ, 0);
    proj_kernel<<<dim3(SEQ/128, DM/128, BAT), 256>>>(h, Wk, SEQ, 1);
    proj_kernel<<<dim3(SEQ/128, DM/128, BAT), 256>>>(h, Wv, SEQ, 2);
    proj_kernel<<<dim3(SKR/128, DM/128, BAT), 256>>>(r, Wr, SKR, 3);

    seg_kernel<<<BAT, SEQ>>>(seg);
    ckdots_kernel<<<dim3((SKR + 7) / 8, BNH), 256>>>(rwb, rrb);
    ef_kernel<<<dim3(SEQ / 8, BNH), 256>>>(rsb, se);

    score_kernel<<<dim3(36, 1, BNH), 256>>>();
    softmax_kernel<<<dim3(SEQ, BNH), 256>>>();
    pv_kernel<<<dim3(SEQ/128, 1, BNH), 256>>>();

    out_kernel<<<dim3((SEQ*BAT)/128, DM/128), 256>>>(Wo, h);
    ln_kernel<<<SEQ*BAT, 256>>>(lns, lnb, out);
}

// round 5
// speedup vs baseline: 2.5289x; 1.7427x over previous
#include <cuda_runtime.h>
#include <math.h>
#include <stdint.h>

#define SEQ   1024
#define BAT   4
#define DM    1024
#define NHEAD 16
#define HD    64
#define BNH   (BAT*NHEAD)   // 64
#define SKR   1152
#define SCALE_F 0.125f
#define NEG_BIG -1.0e30f

// ---------------- scratch ----------------
__device__ float g_q [BNH*SEQ*HD];
__device__ float g_k [BNH*SEQ*HD];
__device__ float g_v [BNH*SEQ*HD];
__device__ float g_kr[BNH*SKR*HD];
__device__ float g_ck [BNH*SEQ];
__device__ float g_ckr[BNH*SKR];
__device__ float g_ef [BNH*SEQ*2];
__device__ float g_a  [BAT*SEQ];
__device__ float g_sc [(size_t)BNH*SEQ*SEQ];
__device__ float g_av [BNH*SEQ*HD];
__device__ float g_ao [SEQ*BAT*DM];

// tf32 mma.sync m16n8k8, fp32 accumulate (in-place)
__device__ __forceinline__ void mma_tf32(float* c, const uint32_t* a, uint32_t b0, uint32_t b1)
{
    asm volatile(
        "mma.sync.aligned.m16n8k8.row.col.f32.tf32.tf32.f32 "
        "{%0,%1,%2,%3}, {%4,%5,%6,%7}, {%8,%9}, {%0,%1,%2,%3};"
        : "+f"(c[0]), "+f"(c[1]), "+f"(c[2]), "+f"(c[3])
        : "r"(a[0]), "r"(a[1]), "r"(a[2]), "r"(a[3]), "r"(b0), "r"(b1));
}

// ---------------- projection GEMM (tf32 tensor cores) ----------------
// out[b,n,row,d] = sum_k in[row,b,k] * W[k, n*64+d]; 128x128 tile, 8 warps (4x2)
__global__ __launch_bounds__(256) void proj_mma(const float* __restrict__ in,
                                                const float* __restrict__ W,
                                                int nrows, int sel)
{
    float* out = (sel == 0) ? g_q : (sel == 1) ? g_k : (sel == 2) ? g_v : g_kr;
    int b    = blockIdx.z;
    int row0 = blockIdx.x * 128;
    int c0   = blockIdx.y * 128;
    __shared__ __align__(16) float As[128][36];   // [row][k], stride 36 (==4 mod 32)
    __shared__ __align__(16) float Bs[32][136];   // [k][n],  stride 136 (==8 mod 32)

    int tid  = threadIdx.x;
    int lane = tid & 31, wid = tid >> 5;
    int wm = wid >> 1, wn = wid & 1;
    int g  = lane >> 2, tg = lane & 3;

    float acc[2][8][4];
#pragma unroll
    for (int mt = 0; mt < 2; mt++)
#pragma unroll
        for (int nt = 0; nt < 8; nt++)
#pragma unroll
            for (int e = 0; e < 4; e++) acc[mt][nt][e] = 0.f;

    for (int k0 = 0; k0 < DM; k0 += 32) {
#pragma unroll
        for (int q = 0; q < 4; q++) {
            int idx = q * 256 + tid;
            int rr = idx >> 3, k4 = (idx & 7) * 4;
            *(float4*)&As[rr][k4] =
                *(const float4*)(in + ((size_t)(row0 + rr) * BAT + b) * DM + k0 + k4);
        }
#pragma unroll
        for (int q = 0; q < 4; q++) {
            int idx = q * 256 + tid;
            int kk = idx >> 5, c4 = (idx & 31) * 4;
            *(float4*)&Bs[kk][c4] = *(const float4*)(W + (size_t)(k0 + kk) * 1024 + c0 + c4);
        }
        __syncthreads();
#pragma unroll
        for (int k8 = 0; k8 < 4; k8++) {
            uint32_t a[2][4];
#pragma unroll
            for (int mt = 0; mt < 2; mt++) {
                int r0 = wm * 32 + mt * 16 + g;
                int kk = k8 * 8 + tg;
                a[mt][0] = __float_as_uint(As[r0][kk]);
                a[mt][1] = __float_as_uint(As[r0 + 8][kk]);
                a[mt][2] = __float_as_uint(As[r0][kk + 4]);
                a[mt][3] = __float_as_uint(As[r0 + 8][kk + 4]);
            }
#pragma unroll
            for (int nt = 0; nt < 8; nt++) {
                int nn = wn * 64 + nt * 8 + g;
                uint32_t b0 = __float_as_uint(Bs[k8 * 8 + tg][nn]);
                uint32_t b1 = __float_as_uint(Bs[k8 * 8 + tg + 4][nn]);
#pragma unroll
                for (int mt = 0; mt < 2; mt++) mma_tf32(acc[mt][nt], a[mt], b0, b1);
            }
        }
        __syncthreads();
    }
    int head = (c0 + wn * 64) >> 6;
    float* op = out + ((size_t)(b * NHEAD + head) * nrows + row0 + wm * 32) * HD;
#pragma unroll
    for (int mt = 0; mt < 2; mt++) {
#pragma unroll
        for (int nt = 0; nt < 8; nt++) {
            int d = nt * 8 + 2 * tg;
            float2 lo = make_float2(acc[mt][nt][0], acc[mt][nt][1]);
            float2 hi = make_float2(acc[mt][nt][2], acc[mt][nt][3]);
            *(float2*)(op + (size_t)(mt * 16 + g) * HD + d)     = lo;
            *(float2*)(op + (size_t)(mt * 16 + g + 8) * HD + d) = hi;
        }
    }
}

// ---------------- segment labels -----------------
__global__ void seg_kernel(const float* __restrict__ seg)
{
    int b = blockIdx.x;
    int i = threadIdx.x;
    g_a[b * SEQ + i] = seg[((size_t)i * BAT + b) * 2 + 1];
}

// ---------------- ck / ckr dot products --------------------------
__global__ __launch_bounds__(256) void ckdots_kernel(const float* __restrict__ rwb,
                                                     const float* __restrict__ rrb)
{
    int bn = blockIdx.y;
    int n  = bn & (NHEAD - 1);
    int wid  = threadIdx.x >> 5;
    int lane = threadIdx.x & 31;
    int j = blockIdx.x * 8 + wid;
    if (j >= SKR) return;
    {
        const float* kr = g_kr + ((size_t)bn * SKR + j) * HD;
        float s = rrb[n * HD + lane] * kr[lane] + rrb[n * HD + 32 + lane] * kr[32 + lane];
#pragma unroll
        for (int o = 16; o; o >>= 1) s += __shfl_down_sync(0xffffffffu, s, o);
        if (lane == 0) g_ckr[bn * SKR + j] = s;
    }
    if (j < SEQ) {
        const float* kp = g_k + ((size_t)bn * SEQ + j) * HD;
        float s = rwb[n * HD + lane] * kp[lane] + rwb[n * HD + 32 + lane] * kp[32 + lane];
#pragma unroll
        for (int o = 16; o; o >>= 1) s += __shfl_down_sync(0xffffffffu, s, o);
        if (lane == 0) g_ck[bn * SEQ + j] = s;
    }
}

// ---------------- ef[i,s] = (q_i + rsb) . seg_embed[s] ------
__global__ __launch_bounds__(256) void ef_kernel(const float* __restrict__ rsb,
                                                 const float* __restrict__ se)
{
    int bn = blockIdx.y;
    int n  = bn & (NHEAD - 1);
    int wid  = threadIdx.x >> 5;
    int lane = threadIdx.x & 31;
    int i = blockIdx.x * 8 + wid;
    const float* qp = g_q + ((size_t)bn * SEQ + i) * HD;
    float q0 = qp[lane] + rsb[n * HD + lane];
    float q1 = qp[32 + lane] + rsb[n * HD + 32 + lane];
    float e0 = q0 * se[(0 * NHEAD + n) * HD + lane] + q1 * se[(0 * NHEAD + n) * HD + 32 + lane];
    float e1 = q0 * se[(1 * NHEAD + n) * HD + lane] + q1 * se[(1 * NHEAD + n) * HD + 32 + lane];
#pragma unroll
    for (int o = 16; o; o >>= 1) {
        e0 += __shfl_down_sync(0xffffffffu, e0, o);
        e1 += __shfl_down_sync(0xffffffffu, e1, o);
    }
    if (lane == 0) {
        g_ef[((size_t)bn * SEQ + i) * 2 + 0] = e0;
        g_ef[((size_t)bn * SEQ + i) * 2 + 1] = e1;
    }
}

// ---------------- fused score kernel: 128x128 tile, 8x8 microtile (FFMA) -------
__global__ __launch_bounds__(256) void score_kernel()
{
    int bn = blockIdx.z;
    int b  = bn >> 4;
    int t  = blockIdx.x;
    int it = 0;
    while ((it + 1) * (it + 2) / 2 <= t) it++;
    int jt = t - it * (it + 1) / 2;
    int i0 = it * 128, j0 = jt * 128;
    int pmin = SEQ + j0 - i0 - 127;

    __shared__ __align__(16) float Qs[16][132];
    __shared__ __align__(16) float Ks[16][132];
    __shared__ __align__(16) float KRs[16][260];
    __shared__ float sck[128];
    __shared__ float sckr[256];
    __shared__ float sef[256];
    __shared__ float sai[128];
    __shared__ float saj[128];

    int tid = threadIdx.x;
    int tx = tid & 15, ty = tid >> 4;

    if (tid < 128) {
        sck[tid] = g_ck[(size_t)bn * SEQ + j0 + tid];
        sai[tid] = g_a[b * SEQ + i0 + tid];
        saj[tid] = g_a[b * SEQ + j0 + tid];
    } else {
        int x = tid - 128;
        sef[x]       = g_ef[((size_t)bn * SEQ + i0) * 2 + x];
        sef[x + 128] = g_ef[((size_t)bn * SEQ + i0) * 2 + x + 128];
    }
    if (tid < 255) sckr[tid] = g_ckr[(size_t)bn * SKR + pmin + tid];

    float acc[8][8];
#pragma unroll
    for (int u = 0; u < 8; u++)
#pragma unroll
        for (int v = 0; v < 8; v++) acc[u][v] = 0.f;

    int dbase = (tx - ty) * 8 + 120;

    for (int kb = 0; kb < HD; kb += 16) {
#pragma unroll
        for (int q = 0; q < 2; q++) {
            int f = tid * 2 + q;
            int rr = f >> 2, kk4 = f & 3;
            const float4 tq = *(const float4*)(g_q + ((size_t)bn * SEQ + i0 + rr) * HD + kb + kk4 * 4);
            Qs[kk4 * 4 + 0][rr] = tq.x; Qs[kk4 * 4 + 1][rr] = tq.y;
            Qs[kk4 * 4 + 2][rr] = tq.z; Qs[kk4 * 4 + 3][rr] = tq.w;
            const float4 tk = *(const float4*)(g_k + ((size_t)bn * SEQ + j0 + rr) * HD + kb + kk4 * 4);
            Ks[kk4 * 4 + 0][rr] = tk.x; Ks[kk4 * 4 + 1][rr] = tk.y;
            Ks[kk4 * 4 + 2][rr] = tk.z; Ks[kk4 * 4 + 3][rr] = tk.w;
        }
#pragma unroll
        for (int q = 0; q < 4; q++) {
            float4 tr = make_float4(0.f, 0.f, 0.f, 0.f);
            if (tid < 255)
                tr = *(const float4*)(g_kr + ((size_t)bn * SKR + pmin + tid) * HD + kb + q * 4);
            KRs[q * 4 + 0][tid] = tr.x; KRs[q * 4 + 1][tid] = tr.y;
            KRs[q * 4 + 2][tid] = tr.z; KRs[q * 4 + 3][tid] = tr.w;
        }
        __syncthreads();
#pragma unroll
        for (int kk = 0; kk < 16; kk++) {
            float4 a0 = *(const float4*)&Qs[kk][ty * 8];
            float4 a1 = *(const float4*)&Qs[kk][ty * 8 + 4];
            float4 b0 = *(const float4*)&Ks[kk][tx * 8];
            float4 b1 = *(const float4*)&Ks[kk][tx * 8 + 4];
            float4 d0 = *(const float4*)&KRs[kk][dbase];
            float4 d1 = *(const float4*)&KRs[kk][dbase + 4];
            float4 d2 = *(const float4*)&KRs[kk][dbase + 8];
            float4 d3 = *(const float4*)&KRs[kk][dbase + 12];
            float qv[8] = {a0.x, a0.y, a0.z, a0.w, a1.x, a1.y, a1.z, a1.w};
            float kv[8] = {b0.x, b0.y, b0.z, b0.w, b1.x, b1.y, b1.z, b1.w};
            float dv[16] = {d0.x, d0.y, d0.z, d0.w, d1.x, d1.y, d1.z, d1.w,
                            d2.x, d2.y, d2.z, d2.w, d3.x, d3.y, d3.z, d3.w};
#pragma unroll
            for (int u = 0; u < 8; u++)
#pragma unroll
                for (int v = 0; v < 8; v++)
                    acc[u][v] += qv[u] * (kv[v] + dv[v - u + 7]);
        }
        __syncthreads();
    }

    size_t base = (size_t)bn * SEQ * SEQ;
    int dbase7 = (tx - ty) * 8 + 127;
#pragma unroll
    for (int u = 0; u < 8; u++) {
        int ii = ty * 8 + u;
        int i  = i0 + ii;
        float ai  = sai[ii];
        float ef0 = sef[ii * 2 + 0];
        float ef1 = sef[ii * 2 + 1];
        float row[8];
#pragma unroll
        for (int v = 0; v < 8; v++) {
            int jj = tx * 8 + v;
            int j  = j0 + jj;
            if (j > i) {
                row[v] = NEG_BIG;
            } else {
                float efv = (ai != saj[jj]) ? ef1 : ef0;
                row[v] = (acc[u][v] + sck[jj] + sckr[dbase7 + v - u] + efv) * SCALE_F;
            }
        }
        float* op = &g_sc[base + (size_t)i * SEQ + j0 + tx * 8];
        *(float4*)(op)     = make_float4(row[0], row[1], row[2], row[3]);
        *(float4*)(op + 4) = make_float4(row[4], row[5], row[6], row[7]);
    }
}

// ---------------- softmax per row (causal) -----
__global__ __launch_bounds__(256) void softmax_kernel()
{
    int i  = blockIdx.x;
    int bn = blockIdx.y;
    size_t base = ((size_t)bn * SEQ + i) * SEQ;
    int tid = threadIdx.x;
    int len = i + 1;
    float v[4];
    float m = -3.4e38f;
#pragma unroll
    for (int k = 0; k < 4; k++) {
        int j = tid + k * 256;
        v[k] = (j < len) ? g_sc[base + j] : -3.4e38f;
        m = fmaxf(m, v[k]);
    }
    __shared__ float red[256];
    red[tid] = m; __syncthreads();
    for (int s = 128; s > 0; s >>= 1) { if (tid < s) red[tid] = fmaxf(red[tid], red[tid + s]); __syncthreads(); }
    m = red[0]; __syncthreads();
    float sum = 0.f;
    float e[4];
#pragma unroll
    for (int k = 0; k < 4; k++) {
        int j = tid + k * 256;
        e[k] = (j < len) ? expf(v[k] - m) : 0.f;
        sum += e[k];
    }
    red[tid] = sum; __syncthreads();
    for (int s = 128; s > 0; s >>= 1) { if (tid < s) red[tid] += red[tid + s]; __syncthreads(); }
    float inv = 1.f / red[0];
#pragma unroll
    for (int k = 0; k < 4; k++) {
        int j = tid + k * 256;
        g_sc[base + j] = e[k] * inv;
    }
}

// ---------------- PV GEMM: 128x64 tile, 8x4 microtile ----------------
__global__ __launch_bounds__(256) void pv_kernel()
{
    int bn = blockIdx.z;
    int i0 = blockIdx.x * 128;
    __shared__ __align__(16) float As[16][132];
    __shared__ __align__(16) float Bs[16][68];
    int tid = threadIdx.x;
    int tx = tid & 15, ty = tid >> 4;
    float acc[8][4];
#pragma unroll
    for (int u = 0; u < 8; u++)
#pragma unroll
        for (int v = 0; v < 4; v++) acc[u][v] = 0.f;

    int kmax = i0 + 128;
    for (int k0 = 0; k0 < kmax; k0 += 16) {
#pragma unroll
        for (int q = 0; q < 2; q++) {
            int f = tid * 2 + q;
            int rr = f >> 2, kk4 = f & 3;
            const float4 t = *(const float4*)(g_sc + ((size_t)bn * SEQ + i0 + rr) * SEQ + k0 + kk4 * 4);
            As[kk4 * 4 + 0][rr] = t.x; As[kk4 * 4 + 1][rr] = t.y;
            As[kk4 * 4 + 2][rr] = t.z; As[kk4 * 4 + 3][rr] = t.w;
        }
        {
            int kk = tid >> 4, cc4 = tid & 15;
            *(float4*)&Bs[kk][cc4 * 4] = *(const float4*)(g_v + ((size_t)bn * SEQ + k0 + kk) * HD + cc4 * 4);
        }
        __syncthreads();
#pragma unroll
        for (int kk = 0; kk < 16; kk++) {
            float4 a0 = *(const float4*)&As[kk][ty * 8];
            float4 a1 = *(const float4*)&As[kk][ty * 8 + 4];
            float4 b0 = *(const float4*)&Bs[kk][tx * 4];
            float av[8] = {a0.x, a0.y, a0.z, a0.w, a1.x, a1.y, a1.z, a1.w};
            float bv[4] = {b0.x, b0.y, b0.z, b0.w};
#pragma unroll
            for (int u = 0; u < 8; u++)
#pragma unroll
                for (int v = 0; v < 4; v++) acc[u][v] += av[u] * bv[v];
        }
        __syncthreads();
    }
#pragma unroll
    for (int u = 0; u < 8; u++) {
        float* op = g_av + ((size_t)bn * SEQ + i0 + ty * 8 + u) * HD + tx * 4;
        *(float4*)op = make_float4(acc[u][0], acc[u][1], acc[u][2], acc[u][3]);
    }
}

// ---------------- Wo GEMM + residual (tf32 tensor cores) ----------------
__global__ __launch_bounds__(256) void out_mma(const float* __restrict__ Wo,
                                               const float* __restrict__ hin)
{
    int row0 = blockIdx.x * 128;
    int c0   = blockIdx.y * 128;
    __shared__ __align__(16) float As[128][36];   // [row][k]
    __shared__ __align__(16) float Bs[128][36];   // [n][k]

    int tid  = threadIdx.x;
    int lane = tid & 31, wid = tid >> 5;
    int wm = wid >> 1, wn = wid & 1;
    int g  = lane >> 2, tg = lane & 3;

    float acc[2][8][4];
#pragma unroll
    for (int mt = 0; mt < 2; mt++)
#pragma unroll
        for (int nt = 0; nt < 8; nt++)
#pragma unroll
            for (int e = 0; e < 4; e++) acc[mt][nt][e] = 0.f;

    for (int k0 = 0; k0 < DM; k0 += 32) {
#pragma unroll
        for (int q = 0; q < 4; q++) {           // A from g_av (row = i*BAT + b)
            int idx = q * 256 + tid;
            int rr = idx >> 3, k4 = (idx & 7) * 4;
            int row = row0 + rr;
            int bb = row & 3, ii = row >> 2;
            int kg = k0 + k4;
            int n = kg >> 6, d = kg & 63;
            *(float4*)&As[rr][k4] =
                *(const float4*)(g_av + ((size_t)(bb * NHEAD + n) * SEQ + ii) * HD + d);
        }
#pragma unroll
        for (int q = 0; q < 4; q++) {           // B[n][k] = Wo[c0+n][k]
            int idx = q * 256 + tid;
            int nn = idx >> 3, k4 = (idx & 7) * 4;
            *(float4*)&Bs[nn][k4] =
                *(const float4*)(Wo + (size_t)(c0 + nn) * 1024 + k0 + k4);
        }
        __syncthreads();
#pragma unroll
        for (int k8 = 0; k8 < 4; k8++) {
            uint32_t a[2][4];
#pragma unroll
            for (int mt = 0; mt < 2; mt++) {
                int r0 = wm * 32 + mt * 16 + g;
                int kk = k8 * 8 + tg;
                a[mt][0] = __float_as_uint(As[r0][kk]);
                a[mt][1] = __float_as_uint(As[r0 + 8][kk]);
                a[mt][2] = __float_as_uint(As[r0][kk + 4]);
                a[mt][3] = __float_as_uint(As[r0 + 8][kk + 4]);
            }
#pragma unroll
            for (int nt = 0; nt < 8; nt++) {
                int nn = wn * 64 + nt * 8 + g;
                uint32_t b0 = __float_as_uint(Bs[nn][k8 * 8 + tg]);
                uint32_t b1 = __float_as_uint(Bs[nn][k8 * 8 + tg + 4]);
#pragma unroll
                for (int mt = 0; mt < 2; mt++) mma_tf32(acc[mt][nt], a[mt], b0, b1);
            }
        }
        __syncthreads();
    }
#pragma unroll
    for (int mt = 0; mt < 2; mt++) {
#pragma unroll
        for (int nt = 0; nt < 8; nt++) {
            int col = c0 + wn * 64 + nt * 8 + 2 * tg;
#pragma unroll
            for (int half = 0; half < 2; half++) {
                int row = row0 + wm * 32 + mt * 16 + g + half * 8;
                const float2 hres = *(const float2*)(hin + (size_t)row * DM + col);
                float2 s = make_float2(acc[mt][nt][half * 2 + 0] + hres.x,
                                       acc[mt][nt][half * 2 + 1] + hres.y);
                *(float2*)(g_ao + (size_t)row * DM + col) = s;
            }
        }
    }
}

// ---------------- LayerNorm --------------------------------------------
__global__ __launch_bounds__(256) void ln_kernel(const float* __restrict__ lns,
                                                 const float* __restrict__ lnb,
                                                 float* __restrict__ out)
{
    int row = blockIdx.x;
    int tid = threadIdx.x;
    const float* x = g_ao + (size_t)row * DM;
    float v[4];
    float s = 0.f;
#pragma unroll
    for (int k = 0; k < 4; k++) { v[k] = x[tid + k * 256]; s += v[k]; }
    __shared__ float red[256];
    red[tid] = s; __syncthreads();
    for (int t = 128; t > 0; t >>= 1) { if (tid < t) red[tid] += red[tid + t]; __syncthreads(); }
    float mu = red[0] * (1.f / DM);
    __syncthreads();
    float s2 = 0.f;
#pragma unroll
    for (int k = 0; k < 4; k++) { float d = v[k] - mu; s2 += d * d; }
    red[tid] = s2; __syncthreads();
    for (int t = 128; t > 0; t >>= 1) { if (tid < t) red[tid] += red[tid + t]; __syncthreads(); }
    float var = red[0] * (1.f / DM);
    float inv = rsqrtf(var + 1e-12f);
#pragma unroll
    for (int k = 0; k < 4; k++) {
        int j = tid + k * 256;
        out[(size_t)row * DM + j] = (v[k] - mu) * inv * lns[j] + lnb[j];
    }
}

// ---------------- launch --------------------------------------------------------
extern "C" void kernel_launch(void* const* d_in, const int* in_sizes, int n_in,
                              void* d_out, int out_size)
{
    const float* h   = (const float*)d_in[0];
    const float* r   = (const float*)d_in[1];
    const float* seg = (const float*)d_in[2];
    const float* Wq  = (const float*)d_in[4];
    const float* Wk  = (const float*)d_in[5];
    const float* Wv  = (const float*)d_in[6];
    const float* Wo  = (const float*)d_in[7];
    const float* Wr  = (const float*)d_in[8];
    const float* rwb = (const float*)d_in[9];
    const float* rrb = (const float*)d_in[10];
    const float* rsb = (const float*)d_in[11];
    const float* se  = (const float*)d_in[12];
    const float* lns = (const float*)d_in[13];
    const float* lnb = (const float*)d_in[14];
    float* out = (float*)d_out;

    proj_mma<<<dim3(SEQ/128, DM/128, BAT), 256>>>(h, Wq, SEQ, 0);
    proj_mma<<<dim3(SEQ/128, DM/128, BAT), 256>>>(h, Wk, SEQ, 1);
    proj_mma<<<dim3(SEQ/128, DM/128, BAT), 256>>>(h, Wv, SEQ, 2);
    proj_mma<<<dim3(SKR/128, DM/128, BAT), 256>>>(r, Wr, SKR, 3);

    seg_kernel<<<BAT, SEQ>>>(seg);
    ckdots_kernel<<<dim3((SKR + 7) / 8, BNH), 256>>>(rwb, rrb);
    ef_kernel<<<dim3(SEQ / 8, BNH), 256>>>(rsb, se);

    score_kernel<<<dim3(36, 1, BNH), 256>>>();
    softmax_kernel<<<dim3(SEQ, BNH), 256>>>();
    pv_kernel<<<dim3(SEQ/128, 1, BNH), 256>>>();

    out_mma<<<dim3((SEQ*BAT)/128, DM/128), 256>>>(Wo, h);
    ln_kernel<<<SEQ*BAT, 256>>>(lns, lnb, out);
}

// round 8
// speedup vs baseline: 3.5157x; 1.3902x over previous
#include <cuda_runtime.h>
#include <math.h>
#include <stdint.h>

#define SEQ   1024
#define BAT   4
#define DM    1024
#define NHEAD 16
#define HD    64
#define BNH   (BAT*NHEAD)   // 64
#define SKR   1152
#define SCALE_F 0.125f
#define NEG_BIG -1.0e30f

// ---------------- scratch ----------------
__device__ float g_q [BNH*SEQ*HD];
__device__ float g_k [BNH*SEQ*HD];
__device__ float g_v [BNH*SEQ*HD];
__device__ float g_kr[BNH*SKR*HD];
__device__ float g_ck [BNH*SEQ];
__device__ float g_ckr[BNH*SKR];
__device__ float g_ef [BNH*SEQ*2];
__device__ float g_a  [BAT*SEQ];
__device__ float g_sc [(size_t)BNH*SEQ*SEQ];
__device__ float g_av [BNH*SEQ*HD];
__device__ float g_ao [SEQ*BAT*DM];

// tf32 mma.sync m16n8k8, fp32 accumulate (in-place)
__device__ __forceinline__ void mma_tf32(float* c, const uint32_t* a, uint32_t b0, uint32_t b1)
{
    asm volatile(
        "mma.sync.aligned.m16n8k8.row.col.f32.tf32.tf32.f32 "
        "{%0,%1,%2,%3}, {%4,%5,%6,%7}, {%8,%9}, {%0,%1,%2,%3};"
        : "+f"(c[0]), "+f"(c[1]), "+f"(c[2]), "+f"(c[3])
        : "r"(a[0]), "r"(a[1]), "r"(a[2]), "r"(a[3]), "r"(b0), "r"(b1));
}

// ---------------- projection GEMM (tf32 tensor cores) ----------------
__global__ __launch_bounds__(256) void proj_mma(const float* __restrict__ in,
                                                const float* __restrict__ W,
                                                int nrows, int sel)
{
    float* out = (sel == 0) ? g_q : (sel == 1) ? g_k : (sel == 2) ? g_v : g_kr;
    int b    = blockIdx.z;
    int row0 = blockIdx.x * 128;
    int c0   = blockIdx.y * 128;
    __shared__ __align__(16) float As[128][36];
    __shared__ __align__(16) float Bs[32][136];

    int tid  = threadIdx.x;
    int lane = tid & 31, wid = tid >> 5;
    int wm = wid >> 1, wn = wid & 1;
    int g  = lane >> 2, tg = lane & 3;

    float acc[2][8][4];
#pragma unroll
    for (int mt = 0; mt < 2; mt++)
#pragma unroll
        for (int nt = 0; nt < 8; nt++)
#pragma unroll
            for (int e = 0; e < 4; e++) acc[mt][nt][e] = 0.f;

    for (int k0 = 0; k0 < DM; k0 += 32) {
#pragma unroll
        for (int q = 0; q < 4; q++) {
            int idx = q * 256 + tid;
            int rr = idx >> 3, k4 = (idx & 7) * 4;
            *(float4*)&As[rr][k4] =
                *(const float4*)(in + ((size_t)(row0 + rr) * BAT + b) * DM + k0 + k4);
        }
#pragma unroll
        for (int q = 0; q < 4; q++) {
            int idx = q * 256 + tid;
            int kk = idx >> 5, c4 = (idx & 31) * 4;
            *(float4*)&Bs[kk][c4] = *(const float4*)(W + (size_t)(k0 + kk) * 1024 + c0 + c4);
        }
        __syncthreads();
#pragma unroll
        for (int k8 = 0; k8 < 4; k8++) {
            uint32_t a[2][4];
#pragma unroll
            for (int mt = 0; mt < 2; mt++) {
                int r0 = wm * 32 + mt * 16 + g;
                int kk = k8 * 8 + tg;
                a[mt][0] = __float_as_uint(As[r0][kk]);
                a[mt][1] = __float_as_uint(As[r0 + 8][kk]);
                a[mt][2] = __float_as_uint(As[r0][kk + 4]);
                a[mt][3] = __float_as_uint(As[r0 + 8][kk + 4]);
            }
#pragma unroll
            for (int nt = 0; nt < 8; nt++) {
                int nn = wn * 64 + nt * 8 + g;
                uint32_t b0 = __float_as_uint(Bs[k8 * 8 + tg][nn]);
                uint32_t b1 = __float_as_uint(Bs[k8 * 8 + tg + 4][nn]);
#pragma unroll
                for (int mt = 0; mt < 2; mt++) mma_tf32(acc[mt][nt], a[mt], b0, b1);
            }
        }
        __syncthreads();
    }
    int head = (c0 + wn * 64) >> 6;
    float* op = out + ((size_t)(b * NHEAD + head) * nrows + row0 + wm * 32) * HD;
#pragma unroll
    for (int mt = 0; mt < 2; mt++) {
#pragma unroll
        for (int nt = 0; nt < 8; nt++) {
            int d = nt * 8 + 2 * tg;
            float2 lo = make_float2(acc[mt][nt][0], acc[mt][nt][1]);
            float2 hi = make_float2(acc[mt][nt][2], acc[mt][nt][3]);
            *(float2*)(op + (size_t)(mt * 16 + g) * HD + d)     = lo;
            *(float2*)(op + (size_t)(mt * 16 + g + 8) * HD + d) = hi;
        }
    }
}

// ---------------- segment labels -----------------
__global__ void seg_kernel(const float* __restrict__ seg)
{
    int b = blockIdx.x;
    int i = threadIdx.x;
    g_a[b * SEQ + i] = seg[((size_t)i * BAT + b) * 2 + 1];
}

// ---------------- ck / ckr dot products --------------------------
__global__ __launch_bounds__(256) void ckdots_kernel(const float* __restrict__ rwb,
                                                     const float* __restrict__ rrb)
{
    int bn = blockIdx.y;
    int n  = bn & (NHEAD - 1);
    int wid  = threadIdx.x >> 5;
    int lane = threadIdx.x & 31;
    int j = blockIdx.x * 8 + wid;
    if (j >= SKR) return;
    {
        const float* kr = g_kr + ((size_t)bn * SKR + j) * HD;
        float s = rrb[n * HD + lane] * kr[lane] + rrb[n * HD + 32 + lane] * kr[32 + lane];
#pragma unroll
        for (int o = 16; o; o >>= 1) s += __shfl_down_sync(0xffffffffu, s, o);
        if (lane == 0) g_ckr[bn * SKR + j] = s;
    }
    if (j < SEQ) {
        const float* kp = g_k + ((size_t)bn * SEQ + j) * HD;
        float s = rwb[n * HD + lane] * kp[lane] + rwb[n * HD + 32 + lane] * kp[32 + lane];
#pragma unroll
        for (int o = 16; o; o >>= 1) s += __shfl_down_sync(0xffffffffu, s, o);
        if (lane == 0) g_ck[bn * SEQ + j] = s;
    }
}

// ---------------- ef[i,s] = (q_i + rsb) . seg_embed[s] ------
__global__ __launch_bounds__(256) void ef_kernel(const float* __restrict__ rsb,
                                                 const float* __restrict__ se)
{
    int bn = blockIdx.y;
    int n  = bn & (NHEAD - 1);
    int wid  = threadIdx.x >> 5;
    int lane = threadIdx.x & 31;
    int i = blockIdx.x * 8 + wid;
    const float* qp = g_q + ((size_t)bn * SEQ + i) * HD;
    float q0 = qp[lane] + rsb[n * HD + lane];
    float q1 = qp[32 + lane] + rsb[n * HD + 32 + lane];
    float e0 = q0 * se[(0 * NHEAD + n) * HD + lane] + q1 * se[(0 * NHEAD + n) * HD + 32 + lane];
    float e1 = q0 * se[(1 * NHEAD + n) * HD + lane] + q1 * se[(1 * NHEAD + n) * HD + 32 + lane];
#pragma unroll
    for (int o = 16; o; o >>= 1) {
        e0 += __shfl_down_sync(0xffffffffu, e0, o);
        e1 += __shfl_down_sync(0xffffffffu, e1, o);
    }
    if (lane == 0) {
        g_ef[((size_t)bn * SEQ + i) * 2 + 0] = e0;
        g_ef[((size_t)bn * SEQ + i) * 2 + 1] = e1;
    }
}

// ---------------- score kernel (tf32 MMA): AC + banded BD via gather ----------
// smem layout (dynamic, floats):
//  Qs[128][68], KB[128][68], BDs[128][260], sck[128], sckr[256], sef[256], sai[128], saj[128]
#define SC_QSTR 68
#define SC_Q    0
#define SC_KB   (128*SC_QSTR)
#define SC_BD   (SC_KB + 128*SC_QSTR)
#define SC_CK   (SC_BD + 128*260)
#define SC_CKR  (SC_CK + 128)
#define SC_EF   (SC_CKR + 256)
#define SC_AI   (SC_EF + 256)
#define SC_AJ   (SC_AI + 128)
#define SC_TOTF (SC_AJ + 128)

__global__ __launch_bounds__(256) void score_mma()
{
    extern __shared__ float sm[];
    float* Qs   = sm + SC_Q;
    float* KB   = sm + SC_KB;
    float* BDs  = sm + SC_BD;
    float* sck  = sm + SC_CK;
    float* sckr = sm + SC_CKR;
    float* sef  = sm + SC_EF;
    float* sai  = sm + SC_AI;
    float* saj  = sm + SC_AJ;

    int bn = blockIdx.z;
    int b  = bn >> 4;
    int t  = blockIdx.x;
    int it = 0;
    while ((it + 1) * (it + 2) / 2 <= t) it++;
    int jt = t - it * (it + 1) / 2;
    int i0 = it * 128, j0 = jt * 128;
    int pmin = SEQ + j0 - i0 - 127;

    int tid  = threadIdx.x;
    int lane = tid & 31, wid = tid >> 5;
    int wm = wid >> 1, wn = wid & 1;
    int g  = lane >> 2, tg = lane & 3;

    if (tid < 128) {
        sck[tid] = g_ck[(size_t)bn * SEQ + j0 + tid];
        sai[tid] = g_a[b * SEQ + i0 + tid];
        saj[tid] = g_a[b * SEQ + j0 + tid];
    } else {
        int x = tid - 128;
        sef[x]       = g_ef[((size_t)bn * SEQ + i0) * 2 + x];
        sef[x + 128] = g_ef[((size_t)bn * SEQ + i0) * 2 + x + 128];
    }
    if (tid < 255) sckr[tid] = g_ckr[(size_t)bn * SKR + pmin + tid];

    // load Q tile 128x64 (stride 68)
#pragma unroll
    for (int q = 0; q < 8; q++) {
        int idx = q * 256 + tid;
        int rr = idx >> 4, k4 = (idx & 15) * 4;
        *(float4*)&Qs[rr * SC_QSTR + k4] =
            *(const float4*)(g_q + ((size_t)bn * SEQ + i0 + rr) * HD + k4);
    }

    // ---- BD halves: BD[ii][h*128+n] = Q_i . KR[pmin + h*128 + n] ----
    int nhalf = (i0 == j0) ? 1 : 2;
    for (int h = 0; h < nhalf; h++) {
#pragma unroll
        for (int q = 0; q < 8; q++) {
            int idx = q * 256 + tid;
            int rr = idx >> 4, k4 = (idx & 15) * 4;
            *(float4*)&KB[rr * SC_QSTR + k4] =
                *(const float4*)(g_kr + ((size_t)bn * SKR + pmin + h * 128 + rr) * HD + k4);
        }
        __syncthreads();

        float bd[2][8][4];
#pragma unroll
        for (int mt = 0; mt < 2; mt++)
#pragma unroll
            for (int nt = 0; nt < 8; nt++)
#pragma unroll
                for (int e = 0; e < 4; e++) bd[mt][nt][e] = 0.f;

#pragma unroll
        for (int k8 = 0; k8 < 8; k8++) {
            uint32_t a[2][4];
            int kk = k8 * 8 + tg;
#pragma unroll
            for (int mt = 0; mt < 2; mt++) {
                int r0 = wm * 32 + mt * 16 + g;
                a[mt][0] = __float_as_uint(Qs[r0 * SC_QSTR + kk]);
                a[mt][1] = __float_as_uint(Qs[(r0 + 8) * SC_QSTR + kk]);
                a[mt][2] = __float_as_uint(Qs[r0 * SC_QSTR + kk + 4]);
                a[mt][3] = __float_as_uint(Qs[(r0 + 8) * SC_QSTR + kk + 4]);
            }
#pragma unroll
            for (int nt = 0; nt < 8; nt++) {
                int nn = wn * 64 + nt * 8 + g;
                uint32_t b0 = __float_as_uint(KB[nn * SC_QSTR + kk]);
                uint32_t b1 = __float_as_uint(KB[nn * SC_QSTR + kk + 4]);
#pragma unroll
                for (int mt = 0; mt < 2; mt++) mma_tf32(bd[mt][nt], a[mt], b0, b1);
            }
        }
#pragma unroll
        for (int mt = 0; mt < 2; mt++) {
#pragma unroll
            for (int nt = 0; nt < 8; nt++) {
                int r = wm * 32 + mt * 16 + g;
                int c = h * 128 + wn * 64 + nt * 8 + 2 * tg;
                *(float2*)&BDs[r * 260 + c]       = make_float2(bd[mt][nt][0], bd[mt][nt][1]);
                *(float2*)&BDs[(r + 8) * 260 + c] = make_float2(bd[mt][nt][2], bd[mt][nt][3]);
            }
        }
        __syncthreads();
    }

    // ---- AC: Q . K^T ----
#pragma unroll
    for (int q = 0; q < 8; q++) {
        int idx = q * 256 + tid;
        int rr = idx >> 4, k4 = (idx & 15) * 4;
        *(float4*)&KB[rr * SC_QSTR + k4] =
            *(const float4*)(g_k + ((size_t)bn * SEQ + j0 + rr) * HD + k4);
    }
    __syncthreads();

    float acc[2][8][4];
#pragma unroll
    for (int mt = 0; mt < 2; mt++)
#pragma unroll
        for (int nt = 0; nt < 8; nt++)
#pragma unroll
            for (int e = 0; e < 4; e++) acc[mt][nt][e] = 0.f;

#pragma unroll
    for (int k8 = 0; k8 < 8; k8++) {
        uint32_t a[2][4];
        int kk = k8 * 8 + tg;
#pragma unroll
        for (int mt = 0; mt < 2; mt++) {
            int r0 = wm * 32 + mt * 16 + g;
            a[mt][0] = __float_as_uint(Qs[r0 * SC_QSTR + kk]);
            a[mt][1] = __float_as_uint(Qs[(r0 + 8) * SC_QSTR + kk]);
            a[mt][2] = __float_as_uint(Qs[r0 * SC_QSTR + kk + 4]);
            a[mt][3] = __float_as_uint(Qs[(r0 + 8) * SC_QSTR + kk + 4]);
        }
#pragma unroll
        for (int nt = 0; nt < 8; nt++) {
            int nn = wn * 64 + nt * 8 + g;
            uint32_t b0 = __float_as_uint(KB[nn * SC_QSTR + kk]);
            uint32_t b1 = __float_as_uint(KB[nn * SC_QSTR + kk + 4]);
#pragma unroll
            for (int mt = 0; mt < 2; mt++) mma_tf32(acc[mt][nt], a[mt], b0, b1);
        }
    }

    // ---- epilogue ----
    size_t base = (size_t)bn * SEQ * SEQ;
#pragma unroll
    for (int mt = 0; mt < 2; mt++) {
#pragma unroll
        for (int nt = 0; nt < 8; nt++) {
            int cc = wn * 64 + nt * 8 + 2 * tg;
#pragma unroll
            for (int half = 0; half < 2; half++) {
                int rr = wm * 32 + mt * 16 + g + half * 8;
                int i  = i0 + rr;
                float ai  = sai[rr];
                float ef0 = sef[rr * 2 + 0];
                float ef1 = sef[rr * 2 + 1];
                float o2[2];
#pragma unroll
                for (int e = 0; e < 2; e++) {
                    int jj = cc + e;
                    int j  = j0 + jj;
                    if (j > i) {
                        o2[e] = NEG_BIG;
                    } else {
                        int d = jj - rr + 127;
                        float bdv = BDs[rr * 260 + d] + sckr[d];
                        float efv = (ai != saj[jj]) ? ef1 : ef0;
                        o2[e] = (acc[mt][nt][half * 2 + e] + bdv + sck[jj] + efv) * SCALE_F;
                    }
                }
                *(float2*)&g_sc[base + (size_t)i * SEQ + j0 + cc] = make_float2(o2[0], o2[1]);
            }
        }
    }
}

// ---------------- softmax per row (causal) -----
__global__ __launch_bounds__(256) void softmax_kernel()
{
    int i  = blockIdx.x;
    int bn = blockIdx.y;
    size_t base = ((size_t)bn * SEQ + i) * SEQ;
    int tid = threadIdx.x;
    int len = i + 1;
    float v[4];
    float m = -3.4e38f;
#pragma unroll
    for (int k = 0; k < 4; k++) {
        int j = tid + k * 256;
        v[k] = (j < len) ? g_sc[base + j] : -3.4e38f;
        m = fmaxf(m, v[k]);
    }
    __shared__ float red[256];
    red[tid] = m; __syncthreads();
    for (int s = 128; s > 0; s >>= 1) { if (tid < s) red[tid] = fmaxf(red[tid], red[tid + s]); __syncthreads(); }
    m = red[0]; __syncthreads();
    float sum = 0.f;
    float e[4];
#pragma unroll
    for (int k = 0; k < 4; k++) {
        int j = tid + k * 256;
        e[k] = (j < len) ? expf(v[k] - m) : 0.f;
        sum += e[k];
    }
    red[tid] = sum; __syncthreads();
    for (int s = 128; s > 0; s >>= 1) { if (tid < s) red[tid] += red[tid + s]; __syncthreads(); }
    float inv = 1.f / red[0];
#pragma unroll
    for (int k = 0; k < 4; k++) {
        int j = tid + k * 256;
        g_sc[base + j] = e[k] * inv;
    }
}

// ---------------- PV GEMM (tf32 MMA): av = P @ V --------------------------------
__global__ __launch_bounds__(256) void pv_mma()
{
    int bn = blockIdx.z;
    int i0 = blockIdx.x * 128;
    __shared__ __align__(16) float As[128][36];
    __shared__ __align__(16) float Bs[64][36];

    int tid  = threadIdx.x;
    int lane = tid & 31, wid = tid >> 5;
    int wm = wid >> 1, wn = wid & 1;
    int g  = lane >> 2, tg = lane & 3;

    float acc[2][4][4];
#pragma unroll
    for (int mt = 0; mt < 2; mt++)
#pragma unroll
        for (int nt = 0; nt < 4; nt++)
#pragma unroll
            for (int e = 0; e < 4; e++) acc[mt][nt][e] = 0.f;

    int kmax = i0 + 128;
    for (int k0 = 0; k0 < kmax; k0 += 32) {
#pragma unroll
        for (int q = 0; q < 4; q++) {
            int idx = q * 256 + tid;
            int rr = idx >> 3, k4 = (idx & 7) * 4;
            *(float4*)&As[rr][k4] =
                *(const float4*)(g_sc + ((size_t)bn * SEQ + i0 + rr) * SEQ + k0 + k4);
        }
#pragma unroll
        for (int q = 0; q < 2; q++) {
            int idx = q * 256 + tid;
            int kk = idx >> 4, d4 = (idx & 15) * 4;
            const float4 v4 = *(const float4*)(g_v + ((size_t)bn * SEQ + k0 + kk) * HD + d4);
            Bs[d4 + 0][kk] = v4.x;
            Bs[d4 + 1][kk] = v4.y;
            Bs[d4 + 2][kk] = v4.z;
            Bs[d4 + 3][kk] = v4.w;
        }
        __syncthreads();
#pragma unroll
        for (int k8 = 0; k8 < 4; k8++) {
            uint32_t a[2][4];
            int kk = k8 * 8 + tg;
#pragma unroll
            for (int mt = 0; mt < 2; mt++) {
                int r0 = wm * 32 + mt * 16 + g;
                a[mt][0] = __float_as_uint(As[r0][kk]);
                a[mt][1] = __float_as_uint(As[r0 + 8][kk]);
                a[mt][2] = __float_as_uint(As[r0][kk + 4]);
                a[mt][3] = __float_as_uint(As[r0 + 8][kk + 4]);
            }
#pragma unroll
            for (int nt = 0; nt < 4; nt++) {
                int nn = wn * 32 + nt * 8 + g;
                uint32_t b0 = __float_as_uint(Bs[nn][kk]);
                uint32_t b1 = __float_as_uint(Bs[nn][kk + 4]);
#pragma unroll
                for (int mt = 0; mt < 2; mt++) mma_tf32(acc[mt][nt], a[mt], b0, b1);
            }
        }
        __syncthreads();
    }
#pragma unroll
    for (int mt = 0; mt < 2; mt++) {
#pragma unroll
        for (int nt = 0; nt < 4; nt++) {
            int c = wn * 32 + nt * 8 + 2 * tg;
#pragma unroll
            for (int half = 0; half < 2; half++) {
                int r = wm * 32 + mt * 16 + g + half * 8;
                *(float2*)(g_av + ((size_t)bn * SEQ + i0 + r) * HD + c) =
                    make_float2(acc[mt][nt][half * 2 + 0], acc[mt][nt][half * 2 + 1]);
            }
        }
    }
}

// ---------------- Wo GEMM + residual (tf32 tensor cores) ----------------
__global__ __launch_bounds__(256) void out_mma(const float* __restrict__ Wo,
                                               const float* __restrict__ hin)
{
    int row0 = blockIdx.x * 128;
    int c0   = blockIdx.y * 128;
    __shared__ __align__(16) float As[128][36];
    __shared__ __align__(16) float Bs[128][36];

    int tid  = threadIdx.x;
    int lane = tid & 31, wid = tid >> 5;
    int wm = wid >> 1, wn = wid & 1;
    int g  = lane >> 2, tg = lane & 3;

    float acc[2][8][4];
#pragma unroll
    for (int mt = 0; mt < 2; mt++)
#pragma unroll
        for (int nt = 0; nt < 8; nt++)
#pragma unroll
            for (int e = 0; e < 4; e++) acc[mt][nt][e] = 0.f;

    for (int k0 = 0; k0 < DM; k0 += 32) {
#pragma unroll
        for (int q = 0; q < 4; q++) {
            int idx = q * 256 + tid;
            int rr = idx >> 3, k4 = (idx & 7) * 4;
            int row = row0 + rr;
            int bb = row & 3, ii = row >> 2;
            int kg = k0 + k4;
            int n = kg >> 6, d = kg & 63;
            *(float4*)&As[rr][k4] =
                *(const float4*)(g_av + ((size_t)(bb * NHEAD + n) * SEQ + ii) * HD + d);
        }
#pragma unroll
        for (int q = 0; q < 4; q++) {
            int idx = q * 256 + tid;
            int nn = idx >> 3, k4 = (idx & 7) * 4;
            *(float4*)&Bs[nn][k4] =
                *(const float4*)(Wo + (size_t)(c0 + nn) * 1024 + k0 + k4);
        }
        __syncthreads();
#pragma unroll
        for (int k8 = 0; k8 < 4; k8++) {
            uint32_t a[2][4];
#pragma unroll
            for (int mt = 0; mt < 2; mt++) {
                int r0 = wm * 32 + mt * 16 + g;
                int kk = k8 * 8 + tg;
                a[mt][0] = __float_as_uint(As[r0][kk]);
                a[mt][1] = __float_as_uint(As[r0 + 8][kk]);
                a[mt][2] = __float_as_uint(As[r0][kk + 4]);
                a[mt][3] = __float_as_uint(As[r0 + 8][kk + 4]);
            }
#pragma unroll
            for (int nt = 0; nt < 8; nt++) {
                int nn = wn * 64 + nt * 8 + g;
                uint32_t b0 = __float_as_uint(Bs[nn][k8 * 8 + tg]);
                uint32_t b1 = __float_as_uint(Bs[nn][k8 * 8 + tg + 4]);
#pragma unroll
                for (int mt = 0; mt < 2; mt++) mma_tf32(acc[mt][nt], a[mt], b0, b1);
            }
        }
        __syncthreads();
    }
#pragma unroll
    for (int mt = 0; mt < 2; mt++) {
#pragma unroll
        for (int nt = 0; nt < 8; nt++) {
            int col = c0 + wn * 64 + nt * 8 + 2 * tg;
#pragma unroll
            for (int half = 0; half < 2; half++) {
                int row = row0 + wm * 32 + mt * 16 + g + half * 8;
                const float2 hres = *(const float2*)(hin + (size_t)row * DM + col);
                float2 s = make_float2(acc[mt][nt][half * 2 + 0] + hres.x,
                                       acc[mt][nt][half * 2 + 1] + hres.y);
                *(float2*)(g_ao + (size_t)row * DM + col) = s;
            }
        }
    }
}

// ---------------- LayerNorm --------------------------------------------
__global__ __launch_bounds__(256) void ln_kernel(const float* __restrict__ lns,
                                                 const float* __restrict__ lnb,
                                                 float* __restrict__ out)
{
    int row = blockIdx.x;
    int tid = threadIdx.x;
    const float* x = g_ao + (size_t)row * DM;
    float v[4];
    float s = 0.f;
#pragma unroll
    for (int k = 0; k < 4; k++) { v[k] = x[tid + k * 256]; s += v[k]; }
    __shared__ float red[256];
    red[tid] = s; __syncthreads();
    for (int t = 128; t > 0; t >>= 1) { if (tid < t) red[tid] += red[tid + t]; __syncthreads(); }
    float mu = red[0] * (1.f / DM);
    __syncthreads();
    float s2 = 0.f;
#pragma unroll
    for (int k = 0; k < 4; k++) { float d = v[k] - mu; s2 += d * d; }
    red[tid] = s2; __syncthreads();
    for (int t = 128; t > 0; t >>= 1) { if (tid < t) red[tid] += red[tid + t]; __syncthreads(); }
    float var = red[0] * (1.f / DM);
    float inv = rsqrtf(var + 1e-12f);
#pragma unroll
    for (int k = 0; k < 4; k++) {
        int j = tid + k * 256;
        out[(size_t)row * DM + j] = (v[k] - mu) * inv * lns[j] + lnb[j];
    }
}

// ---------------- launch --------------------------------------------------------
extern "C" void kernel_launch(void* const* d_in, const int* in_sizes, int n_in,
                              void* d_out, int out_size)
{
    const float* h   = (const float*)d_in[0];
    const float* r   = (const float*)d_in[1];
    const float* seg = (const float*)d_in[2];
    const float* Wq  = (const float*)d_in[4];
    const float* Wk  = (const float*)d_in[5];
    const float* Wv  = (const float*)d_in[6];
    const float* Wo  = (const float*)d_in[7];
    const float* Wr  = (const float*)d_in[8];
    const float* rwb = (const float*)d_in[9];
    const float* rrb = (const float*)d_in[10];
    const float* rsb = (const float*)d_in[11];
    const float* se  = (const float*)d_in[12];
    const float* lns = (const float*)d_in[13];
    const float* lnb = (const float*)d_in[14];
    float* out = (float*)d_out;

    static const size_t score_smem = SC_TOTF * sizeof(float);
    cudaFuncSetAttribute(score_mma, cudaFuncAttributeMaxDynamicSharedMemorySize, (int)score_smem);

    proj_mma<<<dim3(SEQ/128, DM/128, BAT), 256>>>(h, Wq, SEQ, 0);
    proj_mma<<<dim3(SEQ/128, DM/128, BAT), 256>>>(h, Wk, SEQ, 1);
    proj_mma<<<dim3(SEQ/128, DM/128, BAT), 256>>>(h, Wv, SEQ, 2);
    proj_mma<<<dim3(SKR/128, DM/128, BAT), 256>>>(r, Wr, SKR, 3);

    seg_kernel<<<BAT, SEQ>>>(seg);
    ckdots_kernel<<<dim3((SKR + 7) / 8, BNH), 256>>>(rwb, rrb);
    ef_kernel<<<dim3(SEQ / 8, BNH), 256>>>(rsb, se);

    score_mma<<<dim3(36, 1, BNH), 256, score_smem>>>();
    softmax_kernel<<<dim3(SEQ, BNH), 256>>>();
    pv_mma<<<dim3(SEQ/128, 1, BNH), 256>>>();

    out_mma<<<dim3((SEQ*BAT)/128, DM/128), 256>>>(Wo, h);
    ln_kernel<<<SEQ*BAT, 256>>>(lns, lnb, out);
}

// round 9
// speedup vs baseline: 4.2851x; 1.2188x over previous
#include <cuda_runtime.h>
#include <math.h>
#include <stdint.h>

#define SEQ   1024
#define BAT   4
#define DM    1024
#define NHEAD 16
#define HD    64
#define BNH   (BAT*NHEAD)   // 64
#define SKR   1152
#define SCALE_F 0.125f
#define NEG_BIG -1.0e30f

// ---------------- scratch ----------------
__device__ float g_q [BNH*SEQ*HD];
__device__ float g_k [BNH*SEQ*HD];
__device__ float g_v [BNH*SEQ*HD];
__device__ float g_kr[BNH*SKR*HD];
__device__ float g_ck [BNH*SEQ];
__device__ float g_ckr[BNH*SKR];
__device__ float g_ef [BNH*SEQ*2];
__device__ float g_a  [BAT*SEQ];
__device__ float g_av [BNH*SEQ*HD];
__device__ float g_ao [SEQ*BAT*DM];

// tf32 mma.sync m16n8k8, fp32 accumulate (in-place)
__device__ __forceinline__ void mma_tf32(float* c, const uint32_t* a, uint32_t b0, uint32_t b1)
{
    asm volatile(
        "mma.sync.aligned.m16n8k8.row.col.f32.tf32.tf32.f32 "
        "{%0,%1,%2,%3}, {%4,%5,%6,%7}, {%8,%9}, {%0,%1,%2,%3};"
        : "+f"(c[0]), "+f"(c[1]), "+f"(c[2]), "+f"(c[3])
        : "r"(a[0]), "r"(a[1]), "r"(a[2]), "r"(a[3]), "r"(b0), "r"(b1));
}

// ---------------- projection GEMM (tf32 tensor cores) ----------------
__global__ __launch_bounds__(256) void proj_mma(const float* __restrict__ in,
                                                const float* __restrict__ W,
                                                int nrows, int sel)
{
    float* out = (sel == 0) ? g_q : (sel == 1) ? g_k : (sel == 2) ? g_v : g_kr;
    int b    = blockIdx.z;
    int row0 = blockIdx.x * 128;
    int c0   = blockIdx.y * 128;
    __shared__ __align__(16) float As[128][36];
    __shared__ __align__(16) float Bs[32][136];

    int tid  = threadIdx.x;
    int lane = tid & 31, wid = tid >> 5;
    int wm = wid >> 1, wn = wid & 1;
    int g  = lane >> 2, tg = lane & 3;

    float acc[2][8][4];
#pragma unroll
    for (int mt = 0; mt < 2; mt++)
#pragma unroll
        for (int nt = 0; nt < 8; nt++)
#pragma unroll
            for (int e = 0; e < 4; e++) acc[mt][nt][e] = 0.f;

    for (int k0 = 0; k0 < DM; k0 += 32) {
#pragma unroll
        for (int q = 0; q < 4; q++) {
            int idx = q * 256 + tid;
            int rr = idx >> 3, k4 = (idx & 7) * 4;
            *(float4*)&As[rr][k4] =
                *(const float4*)(in + ((size_t)(row0 + rr) * BAT + b) * DM + k0 + k4);
        }
#pragma unroll
        for (int q = 0; q < 4; q++) {
            int idx = q * 256 + tid;
            int kk = idx >> 5, c4 = (idx & 31) * 4;
            *(float4*)&Bs[kk][c4] = *(const float4*)(W + (size_t)(k0 + kk) * 1024 + c0 + c4);
        }
        __syncthreads();
#pragma unroll
        for (int k8 = 0; k8 < 4; k8++) {
            uint32_t a[2][4];
#pragma unroll
            for (int mt = 0; mt < 2; mt++) {
                int r0 = wm * 32 + mt * 16 + g;
                int kk = k8 * 8 + tg;
                a[mt][0] = __float_as_uint(As[r0][kk]);
                a[mt][1] = __float_as_uint(As[r0 + 8][kk]);
                a[mt][2] = __float_as_uint(As[r0][kk + 4]);
                a[mt][3] = __float_as_uint(As[r0 + 8][kk + 4]);
            }
#pragma unroll
            for (int nt = 0; nt < 8; nt++) {
                int nn = wn * 64 + nt * 8 + g;
                uint32_t b0 = __float_as_uint(Bs[k8 * 8 + tg][nn]);
                uint32_t b1 = __float_as_uint(Bs[k8 * 8 + tg + 4][nn]);
#pragma unroll
                for (int mt = 0; mt < 2; mt++) mma_tf32(acc[mt][nt], a[mt], b0, b1);
            }
        }
        __syncthreads();
    }
    int head = (c0 + wn * 64) >> 6;
    float* op = out + ((size_t)(b * NHEAD + head) * nrows + row0 + wm * 32) * HD;
#pragma unroll
    for (int mt = 0; mt < 2; mt++) {
#pragma unroll
        for (int nt = 0; nt < 8; nt++) {
            int d = nt * 8 + 2 * tg;
            float2 lo = make_float2(acc[mt][nt][0], acc[mt][nt][1]);
            float2 hi = make_float2(acc[mt][nt][2], acc[mt][nt][3]);
            *(float2*)(op + (size_t)(mt * 16 + g) * HD + d)     = lo;
            *(float2*)(op + (size_t)(mt * 16 + g + 8) * HD + d) = hi;
        }
    }
}

// ---------------- segment labels -----------------
__global__ void seg_kernel(const float* __restrict__ seg)
{
    int b = blockIdx.x;
    int i = threadIdx.x;
    g_a[b * SEQ + i] = seg[((size_t)i * BAT + b) * 2 + 1];
}

// ---------------- ck / ckr dot products --------------------------
__global__ __launch_bounds__(256) void ckdots_kernel(const float* __restrict__ rwb,
                                                     const float* __restrict__ rrb)
{
    int bn = blockIdx.y;
    int n  = bn & (NHEAD - 1);
    int wid  = threadIdx.x >> 5;
    int lane = threadIdx.x & 31;
    int j = blockIdx.x * 8 + wid;
    if (j >= SKR) return;
    {
        const float* kr = g_kr + ((size_t)bn * SKR + j) * HD;
        float s = rrb[n * HD + lane] * kr[lane] + rrb[n * HD + 32 + lane] * kr[32 + lane];
#pragma unroll
        for (int o = 16; o; o >>= 1) s += __shfl_down_sync(0xffffffffu, s, o);
        if (lane == 0) g_ckr[bn * SKR + j] = s;
    }
    if (j < SEQ) {
        const float* kp = g_k + ((size_t)bn * SEQ + j) * HD;
        float s = rwb[n * HD + lane] * kp[lane] + rwb[n * HD + 32 + lane] * kp[32 + lane];
#pragma unroll
        for (int o = 16; o; o >>= 1) s += __shfl_down_sync(0xffffffffu, s, o);
        if (lane == 0) g_ck[bn * SEQ + j] = s;
    }
}

// ---------------- ef[i,s] = (q_i + rsb) . seg_embed[s] ------
__global__ __launch_bounds__(256) void ef_kernel(const float* __restrict__ rsb,
                                                 const float* __restrict__ se)
{
    int bn = blockIdx.y;
    int n  = bn & (NHEAD - 1);
    int wid  = threadIdx.x >> 5;
    int lane = threadIdx.x & 31;
    int i = blockIdx.x * 8 + wid;
    const float* qp = g_q + ((size_t)bn * SEQ + i) * HD;
    float q0 = qp[lane] + rsb[n * HD + lane];
    float q1 = qp[32 + lane] + rsb[n * HD + 32 + lane];
    float e0 = q0 * se[(0 * NHEAD + n) * HD + lane] + q1 * se[(0 * NHEAD + n) * HD + 32 + lane];
    float e1 = q0 * se[(1 * NHEAD + n) * HD + lane] + q1 * se[(1 * NHEAD + n) * HD + 32 + lane];
#pragma unroll
    for (int o = 16; o; o >>= 1) {
        e0 += __shfl_down_sync(0xffffffffu, e0, o);
        e1 += __shfl_down_sync(0xffffffffu, e1, o);
    }
    if (lane == 0) {
        g_ef[((size_t)bn * SEQ + i) * 2 + 0] = e0;
        g_ef[((size_t)bn * SEQ + i) * 2 + 1] = e1;
    }
}

// ============== fused attention: scores + online softmax + PV =================
// One CTA per (i-block of 128 rows, bn). Iterates j-tiles 0..it.
// smem (floats):
#define AT_QSTR 68
#define AT_Q    0
#define AT_KB   (128*AT_QSTR)            // K tile / KR tile / V (as [64][132])
#define AT_BD   (AT_KB + 128*AT_QSTR)    // [128][260]: BD halves, then P tile
#define AT_M    (AT_BD + 128*260)
#define AT_L    (AT_M + 128)
#define AT_RSC  (AT_L + 128)
#define AT_WRED (AT_RSC + 128)           // [2][128]
#define AT_CK   (AT_WRED + 256)
#define AT_CKR  (AT_CK + 128)            // 256
#define AT_EF   (AT_CKR + 256)
#define AT_AI   (AT_EF + 256)
#define AT_AJ   (AT_AI + 128)
#define AT_TOTF (AT_AJ + 128)

__global__ __launch_bounds__(256, 1) void attn_fused()
{
    extern __shared__ float sm[];
    float* Qs   = sm + AT_Q;
    float* KB   = sm + AT_KB;     // K / KR; later V as [64][132]
    float* BDs  = sm + AT_BD;     // stride 260
    float* smM  = sm + AT_M;
    float* smL  = sm + AT_L;
    float* sRsc = sm + AT_RSC;
    float* wred = sm + AT_WRED;
    float* sck  = sm + AT_CK;
    float* sckr = sm + AT_CKR;
    float* sef  = sm + AT_EF;
    float* sai  = sm + AT_AI;
    float* saj  = sm + AT_AJ;

    int bn = blockIdx.z;
    int b  = bn >> 4;
    int it = (int)(gridDim.x - 1 - blockIdx.x);   // heavy CTAs first
    int i0 = it * 128;

    int tid  = threadIdx.x;
    int lane = tid & 31, wid = tid >> 5;
    int wm = wid >> 1, wn = wid & 1;
    int g  = lane >> 2, tg = lane & 3;

    // persistent per-CTA loads
    if (tid < 128) {
        sai[tid] = g_a[b * SEQ + i0 + tid];
        smM[tid] = -3.0e38f;
        smL[tid] = 0.f;
    } else {
        int x = tid - 128;
        sef[x]       = g_ef[((size_t)bn * SEQ + i0) * 2 + x];
        sef[x + 128] = g_ef[((size_t)bn * SEQ + i0) * 2 + x + 128];
    }
#pragma unroll
    for (int q = 0; q < 8; q++) {
        int idx = q * 256 + tid;
        int rr = idx >> 4, k4 = (idx & 15) * 4;
        *(float4*)&Qs[rr * AT_QSTR + k4] =
            *(const float4*)(g_q + ((size_t)bn * SEQ + i0 + rr) * HD + k4);
    }

    // PV output accumulators (rows x 64 cols / 256 thr)
    float acc_o[2][4][4];
#pragma unroll
    for (int mt = 0; mt < 2; mt++)
#pragma unroll
        for (int nt = 0; nt < 4; nt++)
#pragma unroll
            for (int e = 0; e < 4; e++) acc_o[mt][nt][e] = 0.f;

    int r0base = wm * 32 + g;   // + mt*16 (+8 for half)

    for (int jt = 0; jt <= it; jt++) {
        int j0 = jt * 128;
        int pmin = SEQ + j0 - i0 - 127;

        // per-tile bias loads (safe: previous tile fully synced at loop end)
        if (tid < 128) {
            sck[tid] = g_ck[(size_t)bn * SEQ + j0 + tid];
            saj[tid] = g_a[b * SEQ + j0 + tid];
        }
        if (tid < 255) sckr[tid] = g_ckr[(size_t)bn * SKR + pmin + tid];

        // ---- BD halves ----
        int nhalf = (jt == it) ? 1 : 2;
        for (int h = 0; h < nhalf; h++) {
#pragma unroll
            for (int q = 0; q < 8; q++) {
                int idx = q * 256 + tid;
                int rr = idx >> 4, k4 = (idx & 15) * 4;
                *(float4*)&KB[rr * AT_QSTR + k4] =
                    *(const float4*)(g_kr + ((size_t)bn * SKR + pmin + h * 128 + rr) * HD + k4);
            }
            __syncthreads();

            float bd[2][8][4];
#pragma unroll
            for (int mt = 0; mt < 2; mt++)
#pragma unroll
                for (int nt = 0; nt < 8; nt++)
#pragma unroll
                    for (int e = 0; e < 4; e++) bd[mt][nt][e] = 0.f;
#pragma unroll
            for (int k8 = 0; k8 < 8; k8++) {
                uint32_t a[2][4];
                int kk = k8 * 8 + tg;
#pragma unroll
                for (int mt = 0; mt < 2; mt++) {
                    int r0 = r0base + mt * 16;
                    a[mt][0] = __float_as_uint(Qs[r0 * AT_QSTR + kk]);
                    a[mt][1] = __float_as_uint(Qs[(r0 + 8) * AT_QSTR + kk]);
                    a[mt][2] = __float_as_uint(Qs[r0 * AT_QSTR + kk + 4]);
                    a[mt][3] = __float_as_uint(Qs[(r0 + 8) * AT_QSTR + kk + 4]);
                }
#pragma unroll
                for (int nt = 0; nt < 8; nt++) {
                    int nn = wn * 64 + nt * 8 + g;
                    uint32_t b0 = __float_as_uint(KB[nn * AT_QSTR + kk]);
                    uint32_t b1 = __float_as_uint(KB[nn * AT_QSTR + kk + 4]);
#pragma unroll
                    for (int mt = 0; mt < 2; mt++) mma_tf32(bd[mt][nt], a[mt], b0, b1);
                }
            }
#pragma unroll
            for (int mt = 0; mt < 2; mt++) {
#pragma unroll
                for (int nt = 0; nt < 8; nt++) {
                    int r = r0base + mt * 16;
                    int c = h * 128 + wn * 64 + nt * 8 + 2 * tg;
                    *(float2*)&BDs[r * 260 + c]       = make_float2(bd[mt][nt][0], bd[mt][nt][1]);
                    *(float2*)&BDs[(r + 8) * 260 + c] = make_float2(bd[mt][nt][2], bd[mt][nt][3]);
                }
            }
            __syncthreads();
        }

        // ---- AC: Q.K^T ----
#pragma unroll
        for (int q = 0; q < 8; q++) {
            int idx = q * 256 + tid;
            int rr = idx >> 4, k4 = (idx & 15) * 4;
            *(float4*)&KB[rr * AT_QSTR + k4] =
                *(const float4*)(g_k + ((size_t)bn * SEQ + j0 + rr) * HD + k4);
        }
        __syncthreads();

        float acc[2][8][4];
#pragma unroll
        for (int mt = 0; mt < 2; mt++)
#pragma unroll
            for (int nt = 0; nt < 8; nt++)
#pragma unroll
                for (int e = 0; e < 4; e++) acc[mt][nt][e] = 0.f;
#pragma unroll
        for (int k8 = 0; k8 < 8; k8++) {
            uint32_t a[2][4];
            int kk = k8 * 8 + tg;
#pragma unroll
            for (int mt = 0; mt < 2; mt++) {
                int r0 = r0base + mt * 16;
                a[mt][0] = __float_as_uint(Qs[r0 * AT_QSTR + kk]);
                a[mt][1] = __float_as_uint(Qs[(r0 + 8) * AT_QSTR + kk]);
                a[mt][2] = __float_as_uint(Qs[r0 * AT_QSTR + kk + 4]);
                a[mt][3] = __float_as_uint(Qs[(r0 + 8) * AT_QSTR + kk + 4]);
            }
#pragma unroll
            for (int nt = 0; nt < 8; nt++) {
                int nn = wn * 64 + nt * 8 + g;
                uint32_t b0 = __float_as_uint(KB[nn * AT_QSTR + kk]);
                uint32_t b1 = __float_as_uint(KB[nn * AT_QSTR + kk + 4]);
#pragma unroll
                for (int mt = 0; mt < 2; mt++) mma_tf32(acc[mt][nt], a[mt], b0, b1);
            }
        }

        // ---- combine: scores in regs; per-thread row maxima ----
        float pmax[2][2];
#pragma unroll
        for (int mt = 0; mt < 2; mt++)
#pragma unroll
            for (int half = 0; half < 2; half++) pmax[mt][half] = -3.0e38f;

#pragma unroll
        for (int mt = 0; mt < 2; mt++) {
#pragma unroll
            for (int half = 0; half < 2; half++) {
                int rr = r0base + mt * 16 + half * 8;
                float ai  = sai[rr];
                float ef0 = sef[rr * 2 + 0];
                float ef1 = sef[rr * 2 + 1];
#pragma unroll
                for (int nt = 0; nt < 8; nt++) {
                    int cc = wn * 64 + nt * 8 + 2 * tg;
#pragma unroll
                    for (int e = 0; e < 2; e++) {
                        int jj = cc + e;
                        float s;
                        if (jt == it && jj > rr) {
                            s = NEG_BIG;
                        } else {
                            int d = jj - rr + 127;
                            float efv = (ai != saj[jj]) ? ef1 : ef0;
                            s = (acc[mt][nt][half * 2 + e] + BDs[rr * 260 + d] + sckr[d]
                                 + sck[jj] + efv) * SCALE_F;
                        }
                        acc[mt][nt][half * 2 + e] = s;
                        pmax[mt][half] = fmaxf(pmax[mt][half], s);
                    }
                }
            }
        }
        // reduce max across tg (lanes g*4+tg share rows)
#pragma unroll
        for (int mt = 0; mt < 2; mt++)
#pragma unroll
            for (int half = 0; half < 2; half++) {
                float v = pmax[mt][half];
                v = fmaxf(v, __shfl_xor_sync(0xffffffffu, v, 1));
                v = fmaxf(v, __shfl_xor_sync(0xffffffffu, v, 2));
                pmax[mt][half] = v;
            }
        if (tg == 0) {
#pragma unroll
            for (int mt = 0; mt < 2; mt++)
#pragma unroll
                for (int half = 0; half < 2; half++)
                    wred[wn * 128 + r0base + mt * 16 + half * 8] = pmax[mt][half];
        }
        __syncthreads();
        if (tid < 128) {
            float newm = fmaxf(smM[tid], fmaxf(wred[tid], wred[128 + tid]));
            float rs = __expf(smM[tid] - newm);
            sRsc[tid] = rs;
            smM[tid]  = newm;
            smL[tid] *= rs;
        }
        __syncthreads();

        // ---- p = exp(s-m): write P into BDs, partial sums, rescale acc_o ----
        float psum[2][2] = {{0.f, 0.f}, {0.f, 0.f}};
#pragma unroll
        for (int mt = 0; mt < 2; mt++) {
#pragma unroll
            for (int half = 0; half < 2; half++) {
                int rr = r0base + mt * 16 + half * 8;
                float mrow = smM[rr];
#pragma unroll
                for (int nt = 0; nt < 8; nt++) {
                    int cc = wn * 64 + nt * 8 + 2 * tg;
                    float p0 = __expf(acc[mt][nt][half * 2 + 0] - mrow);
                    float p1 = __expf(acc[mt][nt][half * 2 + 1] - mrow);
                    psum[mt][half] += p0 + p1;
                    *(float2*)&BDs[rr * 260 + cc] = make_float2(p0, p1);
                }
            }
        }
#pragma unroll
        for (int mt = 0; mt < 2; mt++)
#pragma unroll
            for (int half = 0; half < 2; half++) {
                float v = psum[mt][half];
                v += __shfl_xor_sync(0xffffffffu, v, 1);
                v += __shfl_xor_sync(0xffffffffu, v, 2);
                psum[mt][half] = v;
            }
        if (tg == 0) {
#pragma unroll
            for (int mt = 0; mt < 2; mt++)
#pragma unroll
                for (int half = 0; half < 2; half++)
                    wred[wn * 128 + r0base + mt * 16 + half * 8] = psum[mt][half];
        }
        // rescale acc_o by rsc per row
#pragma unroll
        for (int mt = 0; mt < 2; mt++) {
            float rs0 = sRsc[r0base + mt * 16];
            float rs1 = sRsc[r0base + mt * 16 + 8];
#pragma unroll
            for (int nt = 0; nt < 4; nt++) {
                acc_o[mt][nt][0] *= rs0;
                acc_o[mt][nt][1] *= rs0;
                acc_o[mt][nt][2] *= rs1;
                acc_o[mt][nt][3] *= rs1;
            }
        }
        // load V (transposed [d][j]) into KB region, stride 132
#pragma unroll
        for (int q = 0; q < 8; q++) {
            int idx = q * 256 + tid;
            int jj = idx >> 4, d4 = (idx & 15) * 4;
            const float4 v4 = *(const float4*)(g_v + ((size_t)bn * SEQ + j0 + jj) * HD + d4);
            KB[(d4 + 0) * 132 + jj] = v4.x;
            KB[(d4 + 1) * 132 + jj] = v4.y;
            KB[(d4 + 2) * 132 + jj] = v4.z;
            KB[(d4 + 3) * 132 + jj] = v4.w;
        }
        __syncthreads();
        if (tid < 128) smL[tid] += wred[tid] + wred[128 + tid];

        // ---- PV: acc_o += P @ V ----
#pragma unroll
        for (int k8 = 0; k8 < 16; k8++) {
            uint32_t a[2][4];
            int kk = k8 * 8 + tg;
#pragma unroll
            for (int mt = 0; mt < 2; mt++) {
                int r0 = r0base + mt * 16;
                a[mt][0] = __float_as_uint(BDs[r0 * 260 + kk]);
                a[mt][1] = __float_as_uint(BDs[(r0 + 8) * 260 + kk]);
                a[mt][2] = __float_as_uint(BDs[r0 * 260 + kk + 4]);
                a[mt][3] = __float_as_uint(BDs[(r0 + 8) * 260 + kk + 4]);
            }
#pragma unroll
            for (int nt = 0; nt < 4; nt++) {
                int nn = wn * 32 + nt * 8 + g;
                uint32_t b0 = __float_as_uint(KB[nn * 132 + kk]);
                uint32_t b1 = __float_as_uint(KB[nn * 132 + kk + 4]);
#pragma unroll
                for (int mt = 0; mt < 2; mt++) mma_tf32(acc_o[mt][nt], a[mt], b0, b1);
            }
        }
        __syncthreads();   // protect KB/BDs reuse next tile
    }

    // ---- finalize: av = acc_o / l ----
#pragma unroll
    for (int mt = 0; mt < 2; mt++) {
#pragma unroll
        for (int half = 0; half < 2; half++) {
            int rr = r0base + mt * 16 + half * 8;
            float invl = 1.f / smL[rr];
#pragma unroll
            for (int nt = 0; nt < 4; nt++) {
                int c = wn * 32 + nt * 8 + 2 * tg;
                float2 o = make_float2(acc_o[mt][nt][half * 2 + 0] * invl,
                                       acc_o[mt][nt][half * 2 + 1] * invl);
                *(float2*)(g_av + ((size_t)bn * SEQ + i0 + rr) * HD + c) = o;
            }
        }
    }
}

// ---------------- Wo GEMM + residual (tf32 tensor cores) ----------------
__global__ __launch_bounds__(256) void out_mma(const float* __restrict__ Wo,
                                               const float* __restrict__ hin)
{
    int row0 = blockIdx.x * 128;
    int c0   = blockIdx.y * 128;
    __shared__ __align__(16) float As[128][36];
    __shared__ __align__(16) float Bs[128][36];

    int tid  = threadIdx.x;
    int lane = tid & 31, wid = tid >> 5;
    int wm = wid >> 1, wn = wid & 1;
    int g  = lane >> 2, tg = lane & 3;

    float acc[2][8][4];
#pragma unroll
    for (int mt = 0; mt < 2; mt++)
#pragma unroll
        for (int nt = 0; nt < 8; nt++)
#pragma unroll
            for (int e = 0; e < 4; e++) acc[mt][nt][e] = 0.f;

    for (int k0 = 0; k0 < DM; k0 += 32) {
#pragma unroll
        for (int q = 0; q < 4; q++) {
            int idx = q * 256 + tid;
            int rr = idx >> 3, k4 = (idx & 7) * 4;
            int row = row0 + rr;
            int bb = row & 3, ii = row >> 2;
            int kg = k0 + k4;
            int n = kg >> 6, d = kg & 63;
            *(float4*)&As[rr][k4] =
                *(const float4*)(g_av + ((size_t)(bb * NHEAD + n) * SEQ + ii) * HD + d);
        }
#pragma unroll
        for (int q = 0; q < 4; q++) {
            int idx = q * 256 + tid;
            int nn = idx >> 3, k4 = (idx & 7) * 4;
            *(float4*)&Bs[nn][k4] =
                *(const float4*)(Wo + (size_t)(c0 + nn) * 1024 + k0 + k4);
        }
        __syncthreads();
#pragma unroll
        for (int k8 = 0; k8 < 4; k8++) {
            uint32_t a[2][4];
#pragma unroll
            for (int mt = 0; mt < 2; mt++) {
                int r0 = wm * 32 + mt * 16 + g;
                int kk = k8 * 8 + tg;
                a[mt][0] = __float_as_uint(As[r0][kk]);
                a[mt][1] = __float_as_uint(As[r0 + 8][kk]);
                a[mt][2] = __float_as_uint(As[r0][kk + 4]);
                a[mt][3] = __float_as_uint(As[r0 + 8][kk + 4]);
            }
#pragma unroll
            for (int nt = 0; nt < 8; nt++) {
                int nn = wn * 64 + nt * 8 + g;
                uint32_t b0 = __float_as_uint(Bs[nn][k8 * 8 + tg]);
                uint32_t b1 = __float_as_uint(Bs[nn][k8 * 8 + tg + 4]);
#pragma unroll
                for (int mt = 0; mt < 2; mt++) mma_tf32(acc[mt][nt], a[mt], b0, b1);
            }
        }
        __syncthreads();
    }
#pragma unroll
    for (int mt = 0; mt < 2; mt++) {
#pragma unroll
        for (int nt = 0; nt < 8; nt++) {
            int col = c0 + wn * 64 + nt * 8 + 2 * tg;
#pragma unroll
            for (int half = 0; half < 2; half++) {
                int row = row0 + wm * 32 + mt * 16 + g + half * 8;
                const float2 hres = *(const float2*)(hin + (size_t)row * DM + col);
                float2 s = make_float2(acc[mt][nt][half * 2 + 0] + hres.x,
                                       acc[mt][nt][half * 2 + 1] + hres.y);
                *(float2*)(g_ao + (size_t)row * DM + col) = s;
            }
        }
    }
}

// ---------------- LayerNorm --------------------------------------------
__global__ __launch_bounds__(256) void ln_kernel(const float* __restrict__ lns,
                                                 const float* __restrict__ lnb,
                                                 float* __restrict__ out)
{
    int row = blockIdx.x;
    int tid = threadIdx.x;
    const float* x = g_ao + (size_t)row * DM;
    float v[4];
    float s = 0.f;
#pragma unroll
    for (int k = 0; k < 4; k++) { v[k] = x[tid + k * 256]; s += v[k]; }
    __shared__ float red[256];
    red[tid] = s; __syncthreads();
    for (int t = 128; t > 0; t >>= 1) { if (tid < t) red[tid] += red[tid + t]; __syncthreads(); }
    float mu = red[0] * (1.f / DM);
    __syncthreads();
    float s2 = 0.f;
#pragma unroll
    for (int k = 0; k < 4; k++) { float d = v[k] - mu; s2 += d * d; }
    red[tid] = s2; __syncthreads();
    for (int t = 128; t > 0; t >>= 1) { if (tid < t) red[tid] += red[tid + t]; __syncthreads(); }
    float var = red[0] * (1.f / DM);
    float inv = rsqrtf(var + 1e-12f);
#pragma unroll
    for (int k = 0; k < 4; k++) {
        int j = tid + k * 256;
        out[(size_t)row * DM + j] = (v[k] - mu) * inv * lns[j] + lnb[j];
    }
}

// ---------------- launch --------------------------------------------------------
extern "C" void kernel_launch(void* const* d_in, const int* in_sizes, int n_in,
                              void* d_out, int out_size)
{
    const float* h   = (const float*)d_in[0];
    const float* r   = (const float*)d_in[1];
    const float* seg = (const float*)d_in[2];
    const float* Wq  = (const float*)d_in[4];
    const float* Wk  = (const float*)d_in[5];
    const float* Wv  = (const float*)d_in[6];
    const float* Wo  = (const float*)d_in[7];
    const float* Wr  = (const float*)d_in[8];
    const float* rwb = (const float*)d_in[9];
    const float* rrb = (const float*)d_in[10];
    const float* rsb = (const float*)d_in[11];
    const float* se  = (const float*)d_in[12];
    const float* lns = (const float*)d_in[13];
    const float* lnb = (const float*)d_in[14];
    float* out = (float*)d_out;

    static const size_t attn_smem = AT_TOTF * sizeof(float);
    cudaFuncSetAttribute(attn_fused, cudaFuncAttributeMaxDynamicSharedMemorySize, (int)attn_smem);

    proj_mma<<<dim3(SEQ/128, DM/128, BAT), 256>>>(h, Wq, SEQ, 0);
    proj_mma<<<dim3(SEQ/128, DM/128, BAT), 256>>>(h, Wk, SEQ, 1);
    proj_mma<<<dim3(SEQ/128, DM/128, BAT), 256>>>(h, Wv, SEQ, 2);
    proj_mma<<<dim3(SKR/128, DM/128, BAT), 256>>>(r, Wr, SKR, 3);

    seg_kernel<<<BAT, SEQ>>>(seg);
    ckdots_kernel<<<dim3((SKR + 7) / 8, BNH), 256>>>(rwb, rrb);
    ef_kernel<<<dim3(SEQ / 8, BNH), 256>>>(rsb, se);

    attn_fused<<<dim3(SEQ/128, 1, BNH), 256, attn_smem>>>();

    out_mma<<<dim3((SEQ*BAT)/128, DM/128), 256>>>(Wo, h);
    ln_kernel<<<SEQ*BAT, 256>>>(lns, lnb, out);
}

// round 10
// speedup vs baseline: 4.5657x; 1.0655x over previous
#include <cuda_runtime.h>
#include <math.h>
#include <stdint.h>

#define SEQ   1024
#define BAT   4
#define DM    1024
#define NHEAD 16
#define HD    64
#define BNH   (BAT*NHEAD)   // 64
#define SKR   1152
#define SCALE_F 0.125f
#define NEG_BIG -1.0e30f

// ---------------- scratch ----------------
__device__ float g_q [BNH*SEQ*HD];
__device__ float g_k [BNH*SEQ*HD];
__device__ float g_v [BNH*SEQ*HD];
__device__ float g_kr[BNH*SKR*HD];
__device__ float g_ck [BNH*SEQ];
__device__ float g_ckr[BNH*SKR];
__device__ float g_ef [BNH*SEQ*2];
__device__ float g_a  [BAT*SEQ];
__device__ float g_av [BNH*SEQ*HD];
__device__ float g_ao [SEQ*BAT*DM];

// tf32 mma.sync m16n8k8, fp32 accumulate (in-place)
__device__ __forceinline__ void mma_tf32(float* c, const uint32_t* a, uint32_t b0, uint32_t b1)
{
    asm volatile(
        "mma.sync.aligned.m16n8k8.row.col.f32.tf32.tf32.f32 "
        "{%0,%1,%2,%3}, {%4,%5,%6,%7}, {%8,%9}, {%0,%1,%2,%3};"
        : "+f"(c[0]), "+f"(c[1]), "+f"(c[2]), "+f"(c[3])
        : "r"(a[0]), "r"(a[1]), "r"(a[2]), "r"(a[3]), "r"(b0), "r"(b1));
}

__device__ __forceinline__ void cpa16(void* s, const void* g)
{
    uint32_t sa = (uint32_t)__cvta_generic_to_shared(s);
    asm volatile("cp.async.cg.shared.global [%0], [%1], 16;\n" :: "r"(sa), "l"(g));
}
#define CPA_COMMIT asm volatile("cp.async.commit_group;\n" ::: "memory")
#define CPA_WAIT1  asm volatile("cp.async.wait_group 1;\n" ::: "memory")
#define CPA_WAIT0  asm volatile("cp.async.wait_group 0;\n" ::: "memory")

// ---------------- projection GEMM (tf32, cp.async double-buffered) --------------
// mode 0: QKV fused (blockIdx.y in [0,24): sel = y>>3); mode 1: KR (W0 only)
// smem: As[2][128][36], Bs[2][32][136] (dynamic)
#define PJ_AS(s) ((s) * 4608)
#define PJ_BS(s) (9216 + (s) * 4352)
#define PJ_TOTF  17920

__global__ __launch_bounds__(256) void proj_cp(const float* __restrict__ in,
                                               const float* __restrict__ W0,
                                               const float* __restrict__ W1,
                                               const float* __restrict__ W2,
                                               int nrows, int mode)
{
    extern __shared__ float psm[];
    const float* W;
    float* out;
    int c0;
    if (mode == 0) {
        int sel = blockIdx.y >> 3;
        W   = (sel == 0) ? W0 : (sel == 1) ? W1 : W2;
        out = (sel == 0) ? g_q : (sel == 1) ? g_k : g_v;
        c0  = (blockIdx.y & 7) * 128;
    } else {
        W = W0; out = g_kr; c0 = blockIdx.y * 128;
    }
    int b    = blockIdx.z;
    int row0 = blockIdx.x * 128;

    int tid  = threadIdx.x;
    int lane = tid & 31, wid = tid >> 5;
    int wm = wid >> 1, wn = wid & 1;
    int g  = lane >> 2, tg = lane & 3;

    float acc[2][8][4];
#pragma unroll
    for (int mt = 0; mt < 2; mt++)
#pragma unroll
        for (int nt = 0; nt < 8; nt++)
#pragma unroll
            for (int e = 0; e < 4; e++) acc[mt][nt][e] = 0.f;

    // stage loader
    auto load_stage = [&](int s, int k0) {
        float* As = psm + PJ_AS(s);
        float* Bs = psm + PJ_BS(s);
#pragma unroll
        for (int q = 0; q < 4; q++) {
            int idx = q * 256 + tid;
            int rr = idx >> 3, k4 = (idx & 7) * 4;
            cpa16(&As[rr * 36 + k4], in + ((size_t)(row0 + rr) * BAT + b) * DM + k0 + k4);
        }
#pragma unroll
        for (int q = 0; q < 4; q++) {
            int idx = q * 256 + tid;
            int kk = idx >> 5, c4 = (idx & 31) * 4;
            cpa16(&Bs[kk * 136 + c4], W + (size_t)(k0 + kk) * 1024 + c0 + c4);
        }
        CPA_COMMIT;
    };

    load_stage(0, 0);
    int buf = 0;
    for (int k0 = 0; k0 < DM; k0 += 32) {
        bool has_next = (k0 + 32 < DM);
        if (has_next) load_stage(buf ^ 1, k0 + 32);
        if (has_next) { CPA_WAIT1; } else { CPA_WAIT0; }
        __syncthreads();

        const float* As = psm + PJ_AS(buf);
        const float* Bs = psm + PJ_BS(buf);
#pragma unroll
        for (int k8 = 0; k8 < 4; k8++) {
            uint32_t a[2][4];
            int kk = k8 * 8 + tg;
#pragma unroll
            for (int mt = 0; mt < 2; mt++) {
                int r0 = wm * 32 + mt * 16 + g;
                a[mt][0] = __float_as_uint(As[r0 * 36 + kk]);
                a[mt][1] = __float_as_uint(As[(r0 + 8) * 36 + kk]);
                a[mt][2] = __float_as_uint(As[r0 * 36 + kk + 4]);
                a[mt][3] = __float_as_uint(As[(r0 + 8) * 36 + kk + 4]);
            }
#pragma unroll
            for (int nt = 0; nt < 8; nt++) {
                int nn = wn * 64 + nt * 8 + g;
                uint32_t b0 = __float_as_uint(Bs[kk * 136 + nn]);
                uint32_t b1 = __float_as_uint(Bs[(kk + 4) * 136 + nn]);
#pragma unroll
                for (int mt = 0; mt < 2; mt++) mma_tf32(acc[mt][nt], a[mt], b0, b1);
            }
        }
        __syncthreads();   // all reads of buf done before it is refilled
        buf ^= 1;
    }

    int head = (c0 + wn * 64) >> 6;
    float* op = out + ((size_t)(b * NHEAD + head) * nrows + row0 + wm * 32) * HD;
#pragma unroll
    for (int mt = 0; mt < 2; mt++) {
#pragma unroll
        for (int nt = 0; nt < 8; nt++) {
            int d = nt * 8 + 2 * tg;
            float2 lo = make_float2(acc[mt][nt][0], acc[mt][nt][1]);
            float2 hi = make_float2(acc[mt][nt][2], acc[mt][nt][3]);
            *(float2*)(op + (size_t)(mt * 16 + g) * HD + d)     = lo;
            *(float2*)(op + (size_t)(mt * 16 + g + 8) * HD + d) = hi;
        }
    }
}

// ---------------- segment labels -----------------
__global__ void seg_kernel(const float* __restrict__ seg)
{
    int b = blockIdx.x;
    int i = threadIdx.x;
    g_a[b * SEQ + i] = seg[((size_t)i * BAT + b) * 2 + 1];
}

// ---------------- ck / ckr dot products --------------------------
__global__ __launch_bounds__(256) void ckdots_kernel(const float* __restrict__ rwb,
                                                     const float* __restrict__ rrb)
{
    int bn = blockIdx.y;
    int n  = bn & (NHEAD - 1);
    int wid  = threadIdx.x >> 5;
    int lane = threadIdx.x & 31;
    int j = blockIdx.x * 8 + wid;
    if (j >= SKR) return;
    {
        const float* kr = g_kr + ((size_t)bn * SKR + j) * HD;
        float s = rrb[n * HD + lane] * kr[lane] + rrb[n * HD + 32 + lane] * kr[32 + lane];
#pragma unroll
        for (int o = 16; o; o >>= 1) s += __shfl_down_sync(0xffffffffu, s, o);
        if (lane == 0) g_ckr[bn * SKR + j] = s;
    }
    if (j < SEQ) {
        const float* kp = g_k + ((size_t)bn * SEQ + j) * HD;
        float s = rwb[n * HD + lane] * kp[lane] + rwb[n * HD + 32 + lane] * kp[32 + lane];
#pragma unroll
        for (int o = 16; o; o >>= 1) s += __shfl_down_sync(0xffffffffu, s, o);
        if (lane == 0) g_ck[bn * SEQ + j] = s;
    }
}

// ---------------- ef[i,s] = (q_i + rsb) . seg_embed[s] ------
__global__ __launch_bounds__(256) void ef_kernel(const float* __restrict__ rsb,
                                                 const float* __restrict__ se)
{
    int bn = blockIdx.y;
    int n  = bn & (NHEAD - 1);
    int wid  = threadIdx.x >> 5;
    int lane = threadIdx.x & 31;
    int i = blockIdx.x * 8 + wid;
    const float* qp = g_q + ((size_t)bn * SEQ + i) * HD;
    float q0 = qp[lane] + rsb[n * HD + lane];
    float q1 = qp[32 + lane] + rsb[n * HD + 32 + lane];
    float e0 = q0 * se[(0 * NHEAD + n) * HD + lane] + q1 * se[(0 * NHEAD + n) * HD + 32 + lane];
    float e1 = q0 * se[(1 * NHEAD + n) * HD + lane] + q1 * se[(1 * NHEAD + n) * HD + 32 + lane];
#pragma unroll
    for (int o = 16; o; o >>= 1) {
        e0 += __shfl_down_sync(0xffffffffu, e0, o);
        e1 += __shfl_down_sync(0xffffffffu, e1, o);
    }
    if (lane == 0) {
        g_ef[((size_t)bn * SEQ + i) * 2 + 0] = e0;
        g_ef[((size_t)bn * SEQ + i) * 2 + 1] = e1;
    }
}

// ============== fused attention: scores + online softmax + PV =================
// 512 threads, 16 warps in 4x4 (wm rows, wn cols). One CTA per (128-row block, bn).
#define AT_QSTR 68
#define AT_Q    0
#define AT_KB   (128*AT_QSTR)
#define AT_BD   (AT_KB + 128*AT_QSTR)    // [128][260]
#define AT_M    (AT_BD + 128*260)
#define AT_L    (AT_M + 128)
#define AT_RSC  (AT_L + 128)
#define AT_WRED (AT_RSC + 128)           // [4][128]
#define AT_CK   (AT_WRED + 512)
#define AT_CKR  (AT_CK + 128)            // 256
#define AT_EF   (AT_CKR + 256)
#define AT_AI   (AT_EF + 256)
#define AT_AJ   (AT_AI + 128)
#define AT_TOTF (AT_AJ + 128)

__global__ __launch_bounds__(512, 1) void attn_fused()
{
    extern __shared__ float sm[];
    float* Qs   = sm + AT_Q;
    float* KB   = sm + AT_KB;
    float* BDs  = sm + AT_BD;
    float* smM  = sm + AT_M;
    float* smL  = sm + AT_L;
    float* sRsc = sm + AT_RSC;
    float* wred = sm + AT_WRED;
    float* sck  = sm + AT_CK;
    float* sckr = sm + AT_CKR;
    float* sef  = sm + AT_EF;
    float* sai  = sm + AT_AI;
    float* saj  = sm + AT_AJ;

    int bn = blockIdx.z;
    int b  = bn >> 4;
    int it = (int)(gridDim.x - 1 - blockIdx.x);   // heavy CTAs first
    int i0 = it * 128;

    int tid  = threadIdx.x;
    int lane = tid & 31, wid = tid >> 5;
    int wm = wid >> 2, wn = wid & 3;
    int g  = lane >> 2, tg = lane & 3;

    if (tid < 128) {
        sai[tid] = g_a[b * SEQ + i0 + tid];
        smM[tid] = -3.0e38f;
        smL[tid] = 0.f;
    } else if (tid < 256) {
        int x = tid - 128;
        sef[x]       = g_ef[((size_t)bn * SEQ + i0) * 2 + x];
        sef[x + 128] = g_ef[((size_t)bn * SEQ + i0) * 2 + x + 128];
    }
#pragma unroll
    for (int q = 0; q < 4; q++) {
        int idx = q * 512 + tid;
        int rr = idx >> 4, k4 = (idx & 15) * 4;
        *(float4*)&Qs[rr * AT_QSTR + k4] =
            *(const float4*)(g_q + ((size_t)bn * SEQ + i0 + rr) * HD + k4);
    }

    float acc_o[2][2][4];
#pragma unroll
    for (int mt = 0; mt < 2; mt++)
#pragma unroll
        for (int nt = 0; nt < 2; nt++)
#pragma unroll
            for (int e = 0; e < 4; e++) acc_o[mt][nt][e] = 0.f;

    int r0base = wm * 32 + g;

    for (int jt = 0; jt <= it; jt++) {
        int j0 = jt * 128;
        int pmin = SEQ + j0 - i0 - 127;

        if (tid < 128) {
            sck[tid] = g_ck[(size_t)bn * SEQ + j0 + tid];
            saj[tid] = g_a[b * SEQ + j0 + tid];
        }
        if (tid < 255) sckr[tid] = g_ckr[(size_t)bn * SKR + pmin + tid];

        // ---- BD halves ----
        int nhalf = (jt == it) ? 1 : 2;
        for (int h = 0; h < nhalf; h++) {
#pragma unroll
            for (int q = 0; q < 4; q++) {
                int idx = q * 512 + tid;
                int rr = idx >> 4, k4 = (idx & 15) * 4;
                *(float4*)&KB[rr * AT_QSTR + k4] =
                    *(const float4*)(g_kr + ((size_t)bn * SKR + pmin + h * 128 + rr) * HD + k4);
            }
            __syncthreads();

            float bd[2][4][4];
#pragma unroll
            for (int mt = 0; mt < 2; mt++)
#pragma unroll
                for (int nt = 0; nt < 4; nt++)
#pragma unroll
                    for (int e = 0; e < 4; e++) bd[mt][nt][e] = 0.f;
#pragma unroll
            for (int k8 = 0; k8 < 8; k8++) {
                uint32_t a[2][4];
                int kk = k8 * 8 + tg;
#pragma unroll
                for (int mt = 0; mt < 2; mt++) {
                    int r0 = r0base + mt * 16;
                    a[mt][0] = __float_as_uint(Qs[r0 * AT_QSTR + kk]);
                    a[mt][1] = __float_as_uint(Qs[(r0 + 8) * AT_QSTR + kk]);
                    a[mt][2] = __float_as_uint(Qs[r0 * AT_QSTR + kk + 4]);
                    a[mt][3] = __float_as_uint(Qs[(r0 + 8) * AT_QSTR + kk + 4]);
                }
#pragma unroll
                for (int nt = 0; nt < 4; nt++) {
                    int nn = wn * 32 + nt * 8 + g;
                    uint32_t b0 = __float_as_uint(KB[nn * AT_QSTR + kk]);
                    uint32_t b1 = __float_as_uint(KB[nn * AT_QSTR + kk + 4]);
#pragma unroll
                    for (int mt = 0; mt < 2; mt++) mma_tf32(bd[mt][nt], a[mt], b0, b1);
                }
            }
#pragma unroll
            for (int mt = 0; mt < 2; mt++) {
#pragma unroll
                for (int nt = 0; nt < 4; nt++) {
                    int r = r0base + mt * 16;
                    int c = h * 128 + wn * 32 + nt * 8 + 2 * tg;
                    *(float2*)&BDs[r * 260 + c]       = make_float2(bd[mt][nt][0], bd[mt][nt][1]);
                    *(float2*)&BDs[(r + 8) * 260 + c] = make_float2(bd[mt][nt][2], bd[mt][nt][3]);
                }
            }
            __syncthreads();
        }

        // ---- AC: Q.K^T ----
#pragma unroll
        for (int q = 0; q < 4; q++) {
            int idx = q * 512 + tid;
            int rr = idx >> 4, k4 = (idx & 15) * 4;
            *(float4*)&KB[rr * AT_QSTR + k4] =
                *(const float4*)(g_k + ((size_t)bn * SEQ + j0 + rr) * HD + k4);
        }
        __syncthreads();

        float acc[2][4][4];
#pragma unroll
        for (int mt = 0; mt < 2; mt++)
#pragma unroll
            for (int nt = 0; nt < 4; nt++)
#pragma unroll
                for (int e = 0; e < 4; e++) acc[mt][nt][e] = 0.f;
#pragma unroll
        for (int k8 = 0; k8 < 8; k8++) {
            uint32_t a[2][4];
            int kk = k8 * 8 + tg;
#pragma unroll
            for (int mt = 0; mt < 2; mt++) {
                int r0 = r0base + mt * 16;
                a[mt][0] = __float_as_uint(Qs[r0 * AT_QSTR + kk]);
                a[mt][1] = __float_as_uint(Qs[(r0 + 8) * AT_QSTR + kk]);
                a[mt][2] = __float_as_uint(Qs[r0 * AT_QSTR + kk + 4]);
                a[mt][3] = __float_as_uint(Qs[(r0 + 8) * AT_QSTR + kk + 4]);
            }
#pragma unroll
            for (int nt = 0; nt < 4; nt++) {
                int nn = wn * 32 + nt * 8 + g;
                uint32_t b0 = __float_as_uint(KB[nn * AT_QSTR + kk]);
                uint32_t b1 = __float_as_uint(KB[nn * AT_QSTR + kk + 4]);
#pragma unroll
                for (int mt = 0; mt < 2; mt++) mma_tf32(acc[mt][nt], a[mt], b0, b1);
            }
        }

        // ---- combine: scores in regs; row maxima ----
        float pmax[2][2];
#pragma unroll
        for (int mt = 0; mt < 2; mt++)
#pragma unroll
            for (int half = 0; half < 2; half++) pmax[mt][half] = -3.0e38f;

#pragma unroll
        for (int mt = 0; mt < 2; mt++) {
#pragma unroll
            for (int half = 0; half < 2; half++) {
                int rr = r0base + mt * 16 + half * 8;
                float ai  = sai[rr];
                float ef0 = sef[rr * 2 + 0];
                float ef1 = sef[rr * 2 + 1];
#pragma unroll
                for (int nt = 0; nt < 4; nt++) {
                    int cc = wn * 32 + nt * 8 + 2 * tg;
#pragma unroll
                    for (int e = 0; e < 2; e++) {
                        int jj = cc + e;
                        float s;
                        if (jt == it && jj > rr) {
                            s = NEG_BIG;
                        } else {
                            int d = jj - rr + 127;
                            float efv = (ai != saj[jj]) ? ef1 : ef0;
                            s = (acc[mt][nt][half * 2 + e] + BDs[rr * 260 + d] + sckr[d]
                                 + sck[jj] + efv) * SCALE_F;
                        }
                        acc[mt][nt][half * 2 + e] = s;
                        pmax[mt][half] = fmaxf(pmax[mt][half], s);
                    }
                }
            }
        }
#pragma unroll
        for (int mt = 0; mt < 2; mt++)
#pragma unroll
            for (int half = 0; half < 2; half++) {
                float v = pmax[mt][half];
                v = fmaxf(v, __shfl_xor_sync(0xffffffffu, v, 1));
                v = fmaxf(v, __shfl_xor_sync(0xffffffffu, v, 2));
                pmax[mt][half] = v;
            }
        if (tg == 0) {
#pragma unroll
            for (int mt = 0; mt < 2; mt++)
#pragma unroll
                for (int half = 0; half < 2; half++)
                    wred[wn * 128 + r0base + mt * 16 + half * 8] = pmax[mt][half];
        }
        __syncthreads();
        if (tid < 128) {
            float newm = fmaxf(fmaxf(wred[tid], wred[128 + tid]),
                               fmaxf(wred[256 + tid], wred[384 + tid]));
            newm = fmaxf(smM[tid], newm);
            float rs = __expf(smM[tid] - newm);
            sRsc[tid] = rs;
            smM[tid]  = newm;
            smL[tid] *= rs;
        }
        __syncthreads();

        // ---- p = exp(s-m): write P into BDs, partial sums ----
        float psum[2][2] = {{0.f, 0.f}, {0.f, 0.f}};
#pragma unroll
        for (int mt = 0; mt < 2; mt++) {
#pragma unroll
            for (int half = 0; half < 2; half++) {
                int rr = r0base + mt * 16 + half * 8;
                float mrow = smM[rr];
#pragma unroll
                for (int nt = 0; nt < 4; nt++) {
                    int cc = wn * 32 + nt * 8 + 2 * tg;
                    float p0 = __expf(acc[mt][nt][half * 2 + 0] - mrow);
                    float p1 = __expf(acc[mt][nt][half * 2 + 1] - mrow);
                    psum[mt][half] += p0 + p1;
                    *(float2*)&BDs[rr * 260 + cc] = make_float2(p0, p1);
                }
            }
        }
#pragma unroll
        for (int mt = 0; mt < 2; mt++)
#pragma unroll
            for (int half = 0; half < 2; half++) {
                float v = psum[mt][half];
                v += __shfl_xor_sync(0xffffffffu, v, 1);
                v += __shfl_xor_sync(0xffffffffu, v, 2);
                psum[mt][half] = v;
            }
        if (tg == 0) {
#pragma unroll
            for (int mt = 0; mt < 2; mt++)
#pragma unroll
                for (int half = 0; half < 2; half++)
                    wred[wn * 128 + r0base + mt * 16 + half * 8] = psum[mt][half];
        }
        // rescale acc_o per row
#pragma unroll
        for (int mt = 0; mt < 2; mt++) {
            float rs0 = sRsc[r0base + mt * 16];
            float rs1 = sRsc[r0base + mt * 16 + 8];
#pragma unroll
            for (int nt = 0; nt < 2; nt++) {
                acc_o[mt][nt][0] *= rs0;
                acc_o[mt][nt][1] *= rs0;
                acc_o[mt][nt][2] *= rs1;
                acc_o[mt][nt][3] *= rs1;
            }
        }
        // load V transposed ([d][j], stride 132) into KB
#pragma unroll
        for (int q = 0; q < 4; q++) {
            int idx = q * 512 + tid;
            int jj = idx >> 4, d4 = (idx & 15) * 4;
            const float4 v4 = *(const float4*)(g_v + ((size_t)bn * SEQ + j0 + jj) * HD + d4);
            KB[(d4 + 0) * 132 + jj] = v4.x;
            KB[(d4 + 1) * 132 + jj] = v4.y;
            KB[(d4 + 2) * 132 + jj] = v4.z;
            KB[(d4 + 3) * 132 + jj] = v4.w;
        }
        __syncthreads();
        if (tid < 128)
            smL[tid] += wred[tid] + wred[128 + tid] + wred[256 + tid] + wred[384 + tid];

        // ---- PV: acc_o += P @ V ----
#pragma unroll
        for (int k8 = 0; k8 < 16; k8++) {
            uint32_t a[2][4];
            int kk = k8 * 8 + tg;
#pragma unroll
            for (int mt = 0; mt < 2; mt++) {
                int r0 = r0base + mt * 16;
                a[mt][0] = __float_as_uint(BDs[r0 * 260 + kk]);
                a[mt][1] = __float_as_uint(BDs[(r0 + 8) * 260 + kk]);
                a[mt][2] = __float_as_uint(BDs[r0 * 260 + kk + 4]);
                a[mt][3] = __float_as_uint(BDs[(r0 + 8) * 260 + kk + 4]);
            }
#pragma unroll
            for (int nt = 0; nt < 2; nt++) {
                int nn = wn * 16 + nt * 8 + g;
                uint32_t b0 = __float_as_uint(KB[nn * 132 + kk]);
                uint32_t b1 = __float_as_uint(KB[nn * 132 + kk + 4]);
#pragma unroll
                for (int mt = 0; mt < 2; mt++) mma_tf32(acc_o[mt][nt], a[mt], b0, b1);
            }
        }
        __syncthreads();
    }

    // ---- finalize ----
#pragma unroll
    for (int mt = 0; mt < 2; mt++) {
#pragma unroll
        for (int half = 0; half < 2; half++) {
            int rr = r0base + mt * 16 + half * 8;
            float invl = 1.f / smL[rr];
#pragma unroll
            for (int nt = 0; nt < 2; nt++) {
                int c = wn * 16 + nt * 8 + 2 * tg;
                float2 o = make_float2(acc_o[mt][nt][half * 2 + 0] * invl,
                                       acc_o[mt][nt][half * 2 + 1] * invl);
                *(float2*)(g_av + ((size_t)bn * SEQ + i0 + rr) * HD + c) = o;
            }
        }
    }
}

// ---------------- Wo GEMM + residual (tf32 tensor cores) ----------------
__global__ __launch_bounds__(256) void out_mma(const float* __restrict__ Wo,
                                               const float* __restrict__ hin)
{
    int row0 = blockIdx.x * 128;
    int c0   = blockIdx.y * 128;
    __shared__ __align__(16) float As[128][36];
    __shared__ __align__(16) float Bs[128][36];

    int tid  = threadIdx.x;
    int lane = tid & 31, wid = tid >> 5;
    int wm = wid >> 1, wn = wid & 1;
    int g  = lane >> 2, tg = lane & 3;

    float acc[2][8][4];
#pragma unroll
    for (int mt = 0; mt < 2; mt++)
#pragma unroll
        for (int nt = 0; nt < 8; nt++)
#pragma unroll
            for (int e = 0; e < 4; e++) acc[mt][nt][e] = 0.f;

    for (int k0 = 0; k0 < DM; k0 += 32) {
#pragma unroll
        for (int q = 0; q < 4; q++) {
            int idx = q * 256 + tid;
            int rr = idx >> 3, k4 = (idx & 7) * 4;
            int row = row0 + rr;
            int bb = row & 3, ii = row >> 2;
            int kg = k0 + k4;
            int n = kg >> 6, d = kg & 63;
            *(float4*)&As[rr][k4] =
                *(const float4*)(g_av + ((size_t)(bb * NHEAD + n) * SEQ + ii) * HD + d);
        }
#pragma unroll
        for (int q = 0; q < 4; q++) {
            int idx = q * 256 + tid;
            int nn = idx >> 3, k4 = (idx & 7) * 4;
            *(float4*)&Bs[nn][k4] =
                *(const float4*)(Wo + (size_t)(c0 + nn) * 1024 + k0 + k4);
        }
        __syncthreads();
#pragma unroll
        for (int k8 = 0; k8 < 4; k8++) {
            uint32_t a[2][4];
#pragma unroll
            for (int mt = 0; mt < 2; mt++) {
                int r0 = wm * 32 + mt * 16 + g;
                int kk = k8 * 8 + tg;
                a[mt][0] = __float_as_uint(As[r0][kk]);
                a[mt][1] = __float_as_uint(As[r0 + 8][kk]);
                a[mt][2] = __float_as_uint(As[r0][kk + 4]);
                a[mt][3] = __float_as_uint(As[r0 + 8][kk + 4]);
            }
#pragma unroll
            for (int nt = 0; nt < 8; nt++) {
                int nn = wn * 64 + nt * 8 + g;
                uint32_t b0 = __float_as_uint(Bs[nn][k8 * 8 + tg]);
                uint32_t b1 = __float_as_uint(Bs[nn][k8 * 8 + tg + 4]);
#pragma unroll
                for (int mt = 0; mt < 2; mt++) mma_tf32(acc[mt][nt], a[mt], b0, b1);
            }
        }
        __syncthreads();
    }
#pragma unroll
    for (int mt = 0; mt < 2; mt++) {
#pragma unroll
        for (int nt = 0; nt < 8; nt++) {
            int col = c0 + wn * 64 + nt * 8 + 2 * tg;
#pragma unroll
            for (int half = 0; half < 2; half++) {
                int row = row0 + wm * 32 + mt * 16 + g + half * 8;
                const float2 hres = *(const float2*)(hin + (size_t)row * DM + col);
                float2 s = make_float2(acc[mt][nt][half * 2 + 0] + hres.x,
                                       acc[mt][nt][half * 2 + 1] + hres.y);
                *(float2*)(g_ao + (size_t)row * DM + col) = s;
            }
        }
    }
}

// ---------------- LayerNorm --------------------------------------------
__global__ __launch_bounds__(256) void ln_kernel(const float* __restrict__ lns,
                                                 const float* __restrict__ lnb,
                                                 float* __restrict__ out)
{
    int row = blockIdx.x;
    int tid = threadIdx.x;
    const float* x = g_ao + (size_t)row * DM;
    float v[4];
    float s = 0.f;
#pragma unroll
    for (int k = 0; k < 4; k++) { v[k] = x[tid + k * 256]; s += v[k]; }
    __shared__ float red[256];
    red[tid] = s; __syncthreads();
    for (int t = 128; t > 0; t >>= 1) { if (tid < t) red[tid] += red[tid + t]; __syncthreads(); }
    float mu = red[0] * (1.f / DM);
    __syncthreads();
    float s2 = 0.f;
#pragma unroll
    for (int k = 0; k < 4; k++) { float d = v[k] - mu; s2 += d * d; }
    red[tid] = s2; __syncthreads();
    for (int t = 128; t > 0; t >>= 1) { if (tid < t) red[tid] += red[tid + t]; __syncthreads(); }
    float var = red[0] * (1.f / DM);
    float inv = rsqrtf(var + 1e-12f);
#pragma unroll
    for (int k = 0; k < 4; k++) {
        int j = tid + k * 256;
        out[(size_t)row * DM + j] = (v[k] - mu) * inv * lns[j] + lnb[j];
    }
}

// ---------------- launch --------------------------------------------------------
extern "C" void kernel_launch(void* const* d_in, const int* in_sizes, int n_in,
                              void* d_out, int out_size)
{
    const float* h   = (const float*)d_in[0];
    const float* r   = (const float*)d_in[1];
    const float* seg = (const float*)d_in[2];
    const float* Wq  = (const float*)d_in[4];
    const float* Wk  = (const float*)d_in[5];
    const float* Wv  = (const float*)d_in[6];
    const float* Wo  = (const float*)d_in[7];
    const float* Wr  = (const float*)d_in[8];
    const float* rwb = (const float*)d_in[9];
    const float* rrb = (const float*)d_in[10];
    const float* rsb = (const float*)d_in[11];
    const float* se  = (const float*)d_in[12];
    const float* lns = (const float*)d_in[13];
    const float* lnb = (const float*)d_in[14];
    float* out = (float*)d_out;

    static const size_t attn_smem = AT_TOTF * sizeof(float);
    static const size_t proj_smem = PJ_TOTF * sizeof(float);
    cudaFuncSetAttribute(attn_fused, cudaFuncAttributeMaxDynamicSharedMemorySize, (int)attn_smem);
    cudaFuncSetAttribute(proj_cp,   cudaFuncAttributeMaxDynamicSharedMemorySize, (int)proj_smem);

    // fused QKV projection + KR projection (cp.async double-buffered)
    proj_cp<<<dim3(SEQ/128, 24, BAT), 256, proj_smem>>>(h, Wq, Wk, Wv, SEQ, 0);
    proj_cp<<<dim3(SKR/128,  8, BAT), 256, proj_smem>>>(r, Wr, Wr, Wr, SKR, 1);

    seg_kernel<<<BAT, SEQ>>>(seg);
    ckdots_kernel<<<dim3((SKR + 7) / 8, BNH), 256>>>(rwb, rrb);
    ef_kernel<<<dim3(SEQ / 8, BNH), 256>>>(rsb, se);

    attn_fused<<<dim3(SEQ/128, 1, BNH), 512, attn_smem>>>();

    out_mma<<<dim3((SEQ*BAT)/128, DM/128), 256>>>(Wo, h);
    ln_kernel<<<SEQ*BAT, 256>>>(lns, lnb, out);
}

// round 11
// speedup vs baseline: 4.7009x; 1.0296x over previous
#include <cuda_runtime.h>
#include <math.h>
#include <stdint.h>

#define SEQ   1024
#define BAT   4
#define DM    1024
#define NHEAD 16
#define HD    64
#define BNH   (BAT*NHEAD)   // 64
#define SKR   1152
#define SCALE_F 0.125f
#define NEG_BIG -1.0e30f

// ---------------- scratch ----------------
__device__ float g_q [BNH*SEQ*HD];
__device__ float g_k [BNH*SEQ*HD];
__device__ float g_v [BNH*SEQ*HD];
__device__ float g_kr[BNH*SKR*HD];
__device__ float g_ck [BNH*SEQ];
__device__ float g_ckr[BNH*SKR];
__device__ float g_ef [BNH*SEQ*2];
__device__ float g_a  [BAT*SEQ];
__device__ float g_av [BNH*SEQ*HD];
__device__ float g_ao [SEQ*BAT*DM];

// tf32 mma.sync m16n8k8, fp32 accumulate (in-place)
__device__ __forceinline__ void mma_tf32(float* c, const uint32_t* a, uint32_t b0, uint32_t b1)
{
    asm volatile(
        "mma.sync.aligned.m16n8k8.row.col.f32.tf32.tf32.f32 "
        "{%0,%1,%2,%3}, {%4,%5,%6,%7}, {%8,%9}, {%0,%1,%2,%3};"
        : "+f"(c[0]), "+f"(c[1]), "+f"(c[2]), "+f"(c[3])
        : "r"(a[0]), "r"(a[1]), "r"(a[2]), "r"(a[3]), "r"(b0), "r"(b1));
}

__device__ __forceinline__ void cpa16(void* s, const void* g)
{
    uint32_t sa = (uint32_t)__cvta_generic_to_shared(s);
    asm volatile("cp.async.cg.shared.global [%0], [%1], 16;\n" :: "r"(sa), "l"(g));
}
#define CPA_COMMIT asm volatile("cp.async.commit_group;\n" ::: "memory")
#define CPA_WAIT1  asm volatile("cp.async.wait_group 1;\n" ::: "memory")
#define CPA_WAIT0  asm volatile("cp.async.wait_group 0;\n" ::: "memory")

// ---------------- projection GEMM (tf32, cp.async double-buffered) --------------
#define PJ_AS(s) ((s) * 4608)
#define PJ_BS(s) (9216 + (s) * 4352)
#define PJ_TOTF  17920

__global__ __launch_bounds__(256) void proj_cp(const float* __restrict__ in,
                                               const float* __restrict__ W0,
                                               const float* __restrict__ W1,
                                               const float* __restrict__ W2,
                                               int nrows, int mode)
{
    extern __shared__ float psm[];
    const float* W;
    float* out;
    int c0;
    if (mode == 0) {
        int sel = blockIdx.y >> 3;
        W   = (sel == 0) ? W0 : (sel == 1) ? W1 : W2;
        out = (sel == 0) ? g_q : (sel == 1) ? g_k : g_v;
        c0  = (blockIdx.y & 7) * 128;
    } else {
        W = W0; out = g_kr; c0 = blockIdx.y * 128;
    }
    int b    = blockIdx.z;
    int row0 = blockIdx.x * 128;

    int tid  = threadIdx.x;
    int lane = tid & 31, wid = tid >> 5;
    int wm = wid >> 1, wn = wid & 1;
    int g  = lane >> 2, tg = lane & 3;

    float acc[2][8][4];
#pragma unroll
    for (int mt = 0; mt < 2; mt++)
#pragma unroll
        for (int nt = 0; nt < 8; nt++)
#pragma unroll
            for (int e = 0; e < 4; e++) acc[mt][nt][e] = 0.f;

    auto load_stage = [&](int s, int k0) {
        float* As = psm + PJ_AS(s);
        float* Bs = psm + PJ_BS(s);
#pragma unroll
        for (int q = 0; q < 4; q++) {
            int idx = q * 256 + tid;
            int rr = idx >> 3, k4 = (idx & 7) * 4;
            cpa16(&As[rr * 36 + k4], in + ((size_t)(row0 + rr) * BAT + b) * DM + k0 + k4);
        }
#pragma unroll
        for (int q = 0; q < 4; q++) {
            int idx = q * 256 + tid;
            int kk = idx >> 5, c4 = (idx & 31) * 4;
            cpa16(&Bs[kk * 136 + c4], W + (size_t)(k0 + kk) * 1024 + c0 + c4);
        }
        CPA_COMMIT;
    };

    load_stage(0, 0);
    int buf = 0;
    for (int k0 = 0; k0 < DM; k0 += 32) {
        bool has_next = (k0 + 32 < DM);
        if (has_next) load_stage(buf ^ 1, k0 + 32);
        if (has_next) { CPA_WAIT1; } else { CPA_WAIT0; }
        __syncthreads();

        const float* As = psm + PJ_AS(buf);
        const float* Bs = psm + PJ_BS(buf);
#pragma unroll
        for (int k8 = 0; k8 < 4; k8++) {
            uint32_t a[2][4];
            int kk = k8 * 8 + tg;
#pragma unroll
            for (int mt = 0; mt < 2; mt++) {
                int r0 = wm * 32 + mt * 16 + g;
                a[mt][0] = __float_as_uint(As[r0 * 36 + kk]);
                a[mt][1] = __float_as_uint(As[(r0 + 8) * 36 + kk]);
                a[mt][2] = __float_as_uint(As[r0 * 36 + kk + 4]);
                a[mt][3] = __float_as_uint(As[(r0 + 8) * 36 + kk + 4]);
            }
#pragma unroll
            for (int nt = 0; nt < 8; nt++) {
                int nn = wn * 64 + nt * 8 + g;
                uint32_t b0 = __float_as_uint(Bs[kk * 136 + nn]);
                uint32_t b1 = __float_as_uint(Bs[(kk + 4) * 136 + nn]);
#pragma unroll
                for (int mt = 0; mt < 2; mt++) mma_tf32(acc[mt][nt], a[mt], b0, b1);
            }
        }
        __syncthreads();
        buf ^= 1;
    }

    int head = (c0 + wn * 64) >> 6;
    float* op = out + ((size_t)(b * NHEAD + head) * nrows + row0 + wm * 32) * HD;
#pragma unroll
    for (int mt = 0; mt < 2; mt++) {
#pragma unroll
        for (int nt = 0; nt < 8; nt++) {
            int d = nt * 8 + 2 * tg;
            float2 lo = make_float2(acc[mt][nt][0], acc[mt][nt][1]);
            float2 hi = make_float2(acc[mt][nt][2], acc[mt][nt][3]);
            *(float2*)(op + (size_t)(mt * 16 + g) * HD + d)     = lo;
            *(float2*)(op + (size_t)(mt * 16 + g + 8) * HD + d) = hi;
        }
    }
}

// ---------------- segment labels -----------------
__global__ void seg_kernel(const float* __restrict__ seg)
{
    int b = blockIdx.x;
    int i = threadIdx.x;
    g_a[b * SEQ + i] = seg[((size_t)i * BAT + b) * 2 + 1];
}

// ---------------- ck / ckr dot products --------------------------
__global__ __launch_bounds__(256) void ckdots_kernel(const float* __restrict__ rwb,
                                                     const float* __restrict__ rrb)
{
    int bn = blockIdx.y;
    int n  = bn & (NHEAD - 1);
    int wid  = threadIdx.x >> 5;
    int lane = threadIdx.x & 31;
    int j = blockIdx.x * 8 + wid;
    if (j >= SKR) return;
    {
        const float* kr = g_kr + ((size_t)bn * SKR + j) * HD;
        float s = rrb[n * HD + lane] * kr[lane] + rrb[n * HD + 32 + lane] * kr[32 + lane];
#pragma unroll
        for (int o = 16; o; o >>= 1) s += __shfl_down_sync(0xffffffffu, s, o);
        if (lane == 0) g_ckr[bn * SKR + j] = s;
    }
    if (j < SEQ) {
        const float* kp = g_k + ((size_t)bn * SEQ + j) * HD;
        float s = rwb[n * HD + lane] * kp[lane] + rwb[n * HD + 32 + lane] * kp[32 + lane];
#pragma unroll
        for (int o = 16; o; o >>= 1) s += __shfl_down_sync(0xffffffffu, s, o);
        if (lane == 0) g_ck[bn * SEQ + j] = s;
    }
}

// ---------------- ef[i,s] = (q_i + rsb) . seg_embed[s] ------
__global__ __launch_bounds__(256) void ef_kernel(const float* __restrict__ rsb,
                                                 const float* __restrict__ se)
{
    int bn = blockIdx.y;
    int n  = bn & (NHEAD - 1);
    int wid  = threadIdx.x >> 5;
    int lane = threadIdx.x & 31;
    int i = blockIdx.x * 8 + wid;
    const float* qp = g_q + ((size_t)bn * SEQ + i) * HD;
    float q0 = qp[lane] + rsb[n * HD + lane];
    float q1 = qp[32 + lane] + rsb[n * HD + 32 + lane];
    float e0 = q0 * se[(0 * NHEAD + n) * HD + lane] + q1 * se[(0 * NHEAD + n) * HD + 32 + lane];
    float e1 = q0 * se[(1 * NHEAD + n) * HD + lane] + q1 * se[(1 * NHEAD + n) * HD + 32 + lane];
#pragma unroll
    for (int o = 16; o; o >>= 1) {
        e0 += __shfl_down_sync(0xffffffffu, e0, o);
        e1 += __shfl_down_sync(0xffffffffu, e1, o);
    }
    if (lane == 0) {
        g_ef[((size_t)bn * SEQ + i) * 2 + 0] = e0;
        g_ef[((size_t)bn * SEQ + i) * 2 + 1] = e1;
    }
}

// ============== fused attention: scores + online softmax + PV =================
// 512 threads, 16 warps 4x4. BD band halves REUSED across j-tiles:
// upper half of tile jt == lower half of tile jt+1 (pmin shifts by exactly 128).
// Regions A(cols 0..127)/B(cols 128..255) of BDs alternate lo/hi roles; P is
// written into the dead lo region each tile.
#define AT_QSTR 68
#define AT_Q    0
#define AT_KB   (128*AT_QSTR)
#define AT_BD   (AT_KB + 128*AT_QSTR)    // [128][260]
#define AT_M    (AT_BD + 128*260)
#define AT_L    (AT_M + 128)
#define AT_RSC  (AT_L + 128)
#define AT_WRED (AT_RSC + 128)           // [4][128]
#define AT_CK   (AT_WRED + 512)
#define AT_CKR  (AT_CK + 128)            // 256
#define AT_EF   (AT_CKR + 256)
#define AT_AI   (AT_EF + 256)
#define AT_AJ   (AT_AI + 128)
#define AT_TOTF (AT_AJ + 128)

__global__ __launch_bounds__(512, 1) void attn_fused()
{
    extern __shared__ float sm[];
    float* Qs   = sm + AT_Q;
    float* KB   = sm + AT_KB;
    float* BDs  = sm + AT_BD;
    float* smM  = sm + AT_M;
    float* smL  = sm + AT_L;
    float* sRsc = sm + AT_RSC;
    float* wred = sm + AT_WRED;
    float* sck  = sm + AT_CK;
    float* sckr = sm + AT_CKR;
    float* sef  = sm + AT_EF;
    float* sai  = sm + AT_AI;
    float* saj  = sm + AT_AJ;

    int bn = blockIdx.z;
    int b  = bn >> 4;
    int it = (int)(gridDim.x - 1 - blockIdx.x);   // heavy CTAs first
    int i0 = it * 128;

    int tid  = threadIdx.x;
    int lane = tid & 31, wid = tid >> 5;
    int wm = wid >> 2, wn = wid & 3;
    int g  = lane >> 2, tg = lane & 3;

    if (tid < 128) {
        sai[tid] = g_a[b * SEQ + i0 + tid];
        smM[tid] = -3.0e38f;
        smL[tid] = 0.f;
    } else if (tid < 256) {
        int x = tid - 128;
        sef[x]       = g_ef[((size_t)bn * SEQ + i0) * 2 + x];
        sef[x + 128] = g_ef[((size_t)bn * SEQ + i0) * 2 + x + 128];
    }
#pragma unroll
    for (int q = 0; q < 4; q++) {
        int idx = q * 512 + tid;
        int rr = idx >> 4, k4 = (idx & 15) * 4;
        *(float4*)&Qs[rr * AT_QSTR + k4] =
            *(const float4*)(g_q + ((size_t)bn * SEQ + i0 + rr) * HD + k4);
    }

    float acc_o[2][2][4];
#pragma unroll
    for (int mt = 0; mt < 2; mt++)
#pragma unroll
        for (int nt = 0; nt < 2; nt++)
#pragma unroll
            for (int e = 0; e < 4; e++) acc_o[mt][nt][e] = 0.f;

    int r0base = wm * 32 + g;

    for (int jt = 0; jt <= it; jt++) {
        int j0 = jt * 128;
        int pmin = SEQ + j0 - i0 - 127;
        int loR = jt & 1;      // region holding lower band half this tile
        int hiR = loR ^ 1;

        if (tid < 128) {
            sck[tid] = g_ck[(size_t)bn * SEQ + j0 + tid];
            saj[tid] = g_a[b * SEQ + j0 + tid];
        }
        if (tid < 255) sckr[tid] = g_ckr[(size_t)bn * SKR + pmin + tid];

        // ---- BD: compute only the NEW halves ----
        // jt==0: lo (+hi if it>0). jt in (0,it): hi only. jt==it>0: none (lo reused).
        int hfirst = (jt == 0) ? 0 : 1;
        int hlast  = (jt == 0) ? ((it == 0) ? 0 : 1) : ((jt < it) ? 1 : 0);
        for (int h = hfirst; h <= hlast; h++) {
            int reg = (h == 0) ? loR : hiR;
#pragma unroll
            for (int q = 0; q < 4; q++) {
                int idx = q * 512 + tid;
                int rr = idx >> 4, k4 = (idx & 15) * 4;
                *(float4*)&KB[rr * AT_QSTR + k4] =
                    *(const float4*)(g_kr + ((size_t)bn * SKR + pmin + h * 128 + rr) * HD + k4);
            }
            __syncthreads();

            float bd[2][4][4];
#pragma unroll
            for (int mt = 0; mt < 2; mt++)
#pragma unroll
                for (int nt = 0; nt < 4; nt++)
#pragma unroll
                    for (int e = 0; e < 4; e++) bd[mt][nt][e] = 0.f;
#pragma unroll
            for (int k8 = 0; k8 < 8; k8++) {
                uint32_t a[2][4];
                int kk = k8 * 8 + tg;
#pragma unroll
                for (int mt = 0; mt < 2; mt++) {
                    int r0 = r0base + mt * 16;
                    a[mt][0] = __float_as_uint(Qs[r0 * AT_QSTR + kk]);
                    a[mt][1] = __float_as_uint(Qs[(r0 + 8) * AT_QSTR + kk]);
                    a[mt][2] = __float_as_uint(Qs[r0 * AT_QSTR + kk + 4]);
                    a[mt][3] = __float_as_uint(Qs[(r0 + 8) * AT_QSTR + kk + 4]);
                }
#pragma unroll
                for (int nt = 0; nt < 4; nt++) {
                    int nn = wn * 32 + nt * 8 + g;
                    uint32_t b0 = __float_as_uint(KB[nn * AT_QSTR + kk]);
                    uint32_t b1 = __float_as_uint(KB[nn * AT_QSTR + kk + 4]);
#pragma unroll
                    for (int mt = 0; mt < 2; mt++) mma_tf32(bd[mt][nt], a[mt], b0, b1);
                }
            }
#pragma unroll
            for (int mt = 0; mt < 2; mt++) {
#pragma unroll
                for (int nt = 0; nt < 4; nt++) {
                    int r = r0base + mt * 16;
                    int c = reg * 128 + wn * 32 + nt * 8 + 2 * tg;
                    *(float2*)&BDs[r * 260 + c]       = make_float2(bd[mt][nt][0], bd[mt][nt][1]);
                    *(float2*)&BDs[(r + 8) * 260 + c] = make_float2(bd[mt][nt][2], bd[mt][nt][3]);
                }
            }
            __syncthreads();
        }

        // ---- AC: Q.K^T ----
#pragma unroll
        for (int q = 0; q < 4; q++) {
            int idx = q * 512 + tid;
            int rr = idx >> 4, k4 = (idx & 15) * 4;
            *(float4*)&KB[rr * AT_QSTR + k4] =
                *(const float4*)(g_k + ((size_t)bn * SEQ + j0 + rr) * HD + k4);
        }
        __syncthreads();

        float acc[2][4][4];
#pragma unroll
        for (int mt = 0; mt < 2; mt++)
#pragma unroll
            for (int nt = 0; nt < 4; nt++)
#pragma unroll
                for (int e = 0; e < 4; e++) acc[mt][nt][e] = 0.f;
#pragma unroll
        for (int k8 = 0; k8 < 8; k8++) {
            uint32_t a[2][4];
            int kk = k8 * 8 + tg;
#pragma unroll
            for (int mt = 0; mt < 2; mt++) {
                int r0 = r0base + mt * 16;
                a[mt][0] = __float_as_uint(Qs[r0 * AT_QSTR + kk]);
                a[mt][1] = __float_as_uint(Qs[(r0 + 8) * AT_QSTR + kk]);
                a[mt][2] = __float_as_uint(Qs[r0 * AT_QSTR + kk + 4]);
                a[mt][3] = __float_as_uint(Qs[(r0 + 8) * AT_QSTR + kk + 4]);
            }
#pragma unroll
            for (int nt = 0; nt < 4; nt++) {
                int nn = wn * 32 + nt * 8 + g;
                uint32_t b0 = __float_as_uint(KB[nn * AT_QSTR + kk]);
                uint32_t b1 = __float_as_uint(KB[nn * AT_QSTR + kk + 4]);
#pragma unroll
                for (int mt = 0; mt < 2; mt++) mma_tf32(acc[mt][nt], a[mt], b0, b1);
            }
        }

        // ---- combine: scores in regs; row maxima ----
        float pmax[2][2];
#pragma unroll
        for (int mt = 0; mt < 2; mt++)
#pragma unroll
            for (int half = 0; half < 2; half++) pmax[mt][half] = -3.0e38f;

#pragma unroll
        for (int mt = 0; mt < 2; mt++) {
#pragma unroll
            for (int half = 0; half < 2; half++) {
                int rr = r0base + mt * 16 + half * 8;
                float ai  = sai[rr];
                float ef0 = sef[rr * 2 + 0];
                float ef1 = sef[rr * 2 + 1];
#pragma unroll
                for (int nt = 0; nt < 4; nt++) {
                    int cc = wn * 32 + nt * 8 + 2 * tg;
#pragma unroll
                    for (int e = 0; e < 2; e++) {
                        int jj = cc + e;
                        float s;
                        if (jt == it && jj > rr) {
                            s = NEG_BIG;
                        } else {
                            int d = jj - rr + 127;
                            int col = (d < 128) ? (loR * 128 + d) : (hiR * 128 + d - 128);
                            float efv = (ai != saj[jj]) ? ef1 : ef0;
                            s = (acc[mt][nt][half * 2 + e] + BDs[rr * 260 + col] + sckr[d]
                                 + sck[jj] + efv) * SCALE_F;
                        }
                        acc[mt][nt][half * 2 + e] = s;
                        pmax[mt][half] = fmaxf(pmax[mt][half], s);
                    }
                }
            }
        }
#pragma unroll
        for (int mt = 0; mt < 2; mt++)
#pragma unroll
            for (int half = 0; half < 2; half++) {
                float v = pmax[mt][half];
                v = fmaxf(v, __shfl_xor_sync(0xffffffffu, v, 1));
                v = fmaxf(v, __shfl_xor_sync(0xffffffffu, v, 2));
                pmax[mt][half] = v;
            }
        if (tg == 0) {
#pragma unroll
            for (int mt = 0; mt < 2; mt++)
#pragma unroll
                for (int half = 0; half < 2; half++)
                    wred[wn * 128 + r0base + mt * 16 + half * 8] = pmax[mt][half];
        }
        __syncthreads();
        if (tid < 128) {
            float newm = fmaxf(fmaxf(wred[tid], wred[128 + tid]),
                               fmaxf(wred[256 + tid], wred[384 + tid]));
            newm = fmaxf(smM[tid], newm);
            float rs = __expf(smM[tid] - newm);
            sRsc[tid] = rs;
            smM[tid]  = newm;
            smL[tid] *= rs;
        }
        __syncthreads();

        // ---- p = exp(s-m): write P into dead lo region, partial sums ----
        float psum[2][2] = {{0.f, 0.f}, {0.f, 0.f}};
#pragma unroll
        for (int mt = 0; mt < 2; mt++) {
#pragma unroll
            for (int half = 0; half < 2; half++) {
                int rr = r0base + mt * 16 + half * 8;
                float mrow = smM[rr];
#pragma unroll
                for (int nt = 0; nt < 4; nt++) {
                    int cc = wn * 32 + nt * 8 + 2 * tg;
                    float p0 = __expf(acc[mt][nt][half * 2 + 0] - mrow);
                    float p1 = __expf(acc[mt][nt][half * 2 + 1] - mrow);
                    psum[mt][half] += p0 + p1;
                    *(float2*)&BDs[rr * 260 + loR * 128 + cc] = make_float2(p0, p1);
                }
            }
        }
#pragma unroll
        for (int mt = 0; mt < 2; mt++)
#pragma unroll
            for (int half = 0; half < 2; half++) {
                float v = psum[mt][half];
                v += __shfl_xor_sync(0xffffffffu, v, 1);
                v += __shfl_xor_sync(0xffffffffu, v, 2);
                psum[mt][half] = v;
            }
        if (tg == 0) {
#pragma unroll
            for (int mt = 0; mt < 2; mt++)
#pragma unroll
                for (int half = 0; half < 2; half++)
                    wred[wn * 128 + r0base + mt * 16 + half * 8] = psum[mt][half];
        }
        // rescale acc_o per row
#pragma unroll
        for (int mt = 0; mt < 2; mt++) {
            float rs0 = sRsc[r0base + mt * 16];
            float rs1 = sRsc[r0base + mt * 16 + 8];
#pragma unroll
            for (int nt = 0; nt < 2; nt++) {
                acc_o[mt][nt][0] *= rs0;
                acc_o[mt][nt][1] *= rs0;
                acc_o[mt][nt][2] *= rs1;
                acc_o[mt][nt][3] *= rs1;
            }
        }
        // load V transposed ([d][j], stride 132) into KB
#pragma unroll
        for (int q = 0; q < 4; q++) {
            int idx = q * 512 + tid;
            int jj = idx >> 4, d4 = (idx & 15) * 4;
            const float4 v4 = *(const float4*)(g_v + ((size_t)bn * SEQ + j0 + jj) * HD + d4);
            KB[(d4 + 0) * 132 + jj] = v4.x;
            KB[(d4 + 1) * 132 + jj] = v4.y;
            KB[(d4 + 2) * 132 + jj] = v4.z;
            KB[(d4 + 3) * 132 + jj] = v4.w;
        }
        __syncthreads();
        if (tid < 128)
            smL[tid] += wred[tid] + wred[128 + tid] + wred[256 + tid] + wred[384 + tid];

        // ---- PV: acc_o += P @ V (P lives in lo region) ----
#pragma unroll
        for (int k8 = 0; k8 < 16; k8++) {
            uint32_t a[2][4];
            int kk = k8 * 8 + tg;
#pragma unroll
            for (int mt = 0; mt < 2; mt++) {
                int r0 = r0base + mt * 16;
                a[mt][0] = __float_as_uint(BDs[r0 * 260 + loR * 128 + kk]);
                a[mt][1] = __float_as_uint(BDs[(r0 + 8) * 260 + loR * 128 + kk]);
                a[mt][2] = __float_as_uint(BDs[r0 * 260 + loR * 128 + kk + 4]);
                a[mt][3] = __float_as_uint(BDs[(r0 + 8) * 260 + loR * 128 + kk + 4]);
            }
#pragma unroll
            for (int nt = 0; nt < 2; nt++) {
                int nn = wn * 16 + nt * 8 + g;
                uint32_t b0 = __float_as_uint(KB[nn * 132 + kk]);
                uint32_t b1 = __float_as_uint(KB[nn * 132 + kk + 4]);
#pragma unroll
                for (int mt = 0; mt < 2; mt++) mma_tf32(acc_o[mt][nt], a[mt], b0, b1);
            }
        }
        __syncthreads();
    }

    // ---- finalize ----
#pragma unroll
    for (int mt = 0; mt < 2; mt++) {
#pragma unroll
        for (int half = 0; half < 2; half++) {
            int rr = r0base + mt * 16 + half * 8;
            float invl = 1.f / smL[rr];
#pragma unroll
            for (int nt = 0; nt < 2; nt++) {
                int c = wn * 16 + nt * 8 + 2 * tg;
                float2 o = make_float2(acc_o[mt][nt][half * 2 + 0] * invl,
                                       acc_o[mt][nt][half * 2 + 1] * invl);
                *(float2*)(g_av + ((size_t)bn * SEQ + i0 + rr) * HD + c) = o;
            }
        }
    }
}

// ---------------- Wo GEMM + residual (tf32 tensor cores) ----------------
__global__ __launch_bounds__(256) void out_mma(const float* __restrict__ Wo,
                                               const float* __restrict__ hin)
{
    int row0 = blockIdx.x * 128;
    int c0   = blockIdx.y * 128;
    __shared__ __align__(16) float As[128][36];
    __shared__ __align__(16) float Bs[128][36];

    int tid  = threadIdx.x;
    int lane = tid & 31, wid = tid >> 5;
    int wm = wid >> 1, wn = wid & 1;
    int g  = lane >> 2, tg = lane & 3;

    float acc[2][8][4];
#pragma unroll
    for (int mt = 0; mt < 2; mt++)
#pragma unroll
        for (int nt = 0; nt < 8; nt++)
#pragma unroll
            for (int e = 0; e < 4; e++) acc[mt][nt][e] = 0.f;

    for (int k0 = 0; k0 < DM; k0 += 32) {
#pragma unroll
        for (int q = 0; q < 4; q++) {
            int idx = q * 256 + tid;
            int rr = idx >> 3, k4 = (idx & 7) * 4;
            int row = row0 + rr;
            int bb = row & 3, ii = row >> 2;
            int kg = k0 + k4;
            int n = kg >> 6, d = kg & 63;
            *(float4*)&As[rr][k4] =
                *(const float4*)(g_av + ((size_t)(bb * NHEAD + n) * SEQ + ii) * HD + d);
        }
#pragma unroll
        for (int q = 0; q < 4; q++) {
            int idx = q * 256 + tid;
            int nn = idx >> 3, k4 = (idx & 7) * 4;
            *(float4*)&Bs[nn][k4] =
                *(const float4*)(Wo + (size_t)(c0 + nn) * 1024 + k0 + k4);
        }
        __syncthreads();
#pragma unroll
        for (int k8 = 0; k8 < 4; k8++) {
            uint32_t a[2][4];
#pragma unroll
            for (int mt = 0; mt < 2; mt++) {
                int r0 = wm * 32 + mt * 16 + g;
                int kk = k8 * 8 + tg;
                a[mt][0] = __float_as_uint(As[r0][kk]);
                a[mt][1] = __float_as_uint(As[r0 + 8][kk]);
                a[mt][2] = __float_as_uint(As[r0][kk + 4]);
                a[mt][3] = __float_as_uint(As[r0 + 8][kk + 4]);
            }
#pragma unroll
            for (int nt = 0; nt < 8; nt++) {
                int nn = wn * 64 + nt * 8 + g;
                uint32_t b0 = __float_as_uint(Bs[nn][k8 * 8 + tg]);
                uint32_t b1 = __float_as_uint(Bs[nn][k8 * 8 + tg + 4]);
#pragma unroll
                for (int mt = 0; mt < 2; mt++) mma_tf32(acc[mt][nt], a[mt], b0, b1);
            }
        }
        __syncthreads();
    }
#pragma unroll
    for (int mt = 0; mt < 2; mt++) {
#pragma unroll
        for (int nt = 0; nt < 8; nt++) {
            int col = c0 + wn * 64 + nt * 8 + 2 * tg;
#pragma unroll
            for (int half = 0; half < 2; half++) {
                int row = row0 + wm * 32 + mt * 16 + g + half * 8;
                const float2 hres = *(const float2*)(hin + (size_t)row * DM + col);
                float2 s = make_float2(acc[mt][nt][half * 2 + 0] + hres.x,
                                       acc[mt][nt][half * 2 + 1] + hres.y);
                *(float2*)(g_ao + (size_t)row * DM + col) = s;
            }
        }
    }
}

// ---------------- LayerNorm --------------------------------------------
__global__ __launch_bounds__(256) void ln_kernel(const float* __restrict__ lns,
                                                 const float* __restrict__ lnb,
                                                 float* __restrict__ out)
{
    int row = blockIdx.x;
    int tid = threadIdx.x;
    const float* x = g_ao + (size_t)row * DM;
    float v[4];
    float s = 0.f;
#pragma unroll
    for (int k = 0; k < 4; k++) { v[k] = x[tid + k * 256]; s += v[k]; }
    __shared__ float red[256];
    red[tid] = s; __syncthreads();
    for (int t = 128; t > 0; t >>= 1) { if (tid < t) red[tid] += red[tid + t]; __syncthreads(); }
    float mu = red[0] * (1.f / DM);
    __syncthreads();
    float s2 = 0.f;
#pragma unroll
    for (int k = 0; k < 4; k++) { float d = v[k] - mu; s2 += d * d; }
    red[tid] = s2; __syncthreads();
    for (int t = 128; t > 0; t >>= 1) { if (tid < t) red[tid] += red[tid + t]; __syncthreads(); }
    float var = red[0] * (1.f / DM);
    float inv = rsqrtf(var + 1e-12f);
#pragma unroll
    for (int k = 0; k < 4; k++) {
        int j = tid + k * 256;
        out[(size_t)row * DM + j] = (v[k] - mu) * inv * lns[j] + lnb[j];
    }
}

// ---------------- launch --------------------------------------------------------
extern "C" void kernel_launch(void* const* d_in, const int* in_sizes, int n_in,
                              void* d_out, int out_size)
{
    const float* h   = (const float*)d_in[0];
    const float* r   = (const float*)d_in[1];
    const float* seg = (const float*)d_in[2];
    const float* Wq  = (const float*)d_in[4];
    const float* Wk  = (const float*)d_in[5];
    const float* Wv  = (const float*)d_in[6];
    const float* Wo  = (const float*)d_in[7];
    const float* Wr  = (const float*)d_in[8];
    const float* rwb = (const float*)d_in[9];
    const float* rrb = (const float*)d_in[10];
    const float* rsb = (const float*)d_in[11];
    const float* se  = (const float*)d_in[12];
    const float* lns = (const float*)d_in[13];
    const float* lnb = (const float*)d_in[14];
    float* out = (float*)d_out;

    static const size_t attn_smem = AT_TOTF * sizeof(float);
    static const size_t proj_smem = PJ_TOTF * sizeof(float);
    cudaFuncSetAttribute(attn_fused, cudaFuncAttributeMaxDynamicSharedMemorySize, (int)attn_smem);
    cudaFuncSetAttribute(proj_cp,   cudaFuncAttributeMaxDynamicSharedMemorySize, (int)proj_smem);

    proj_cp<<<dim3(SEQ/128, 24, BAT), 256, proj_smem>>>(h, Wq, Wk, Wv, SEQ, 0);
    proj_cp<<<dim3(SKR/128,  8, BAT), 256, proj_smem>>>(r, Wr, Wr, Wr, SKR, 1);

    seg_kernel<<<BAT, SEQ>>>(seg);
    ckdots_kernel<<<dim3((SKR + 7) / 8, BNH), 256>>>(rwb, rrb);
    ef_kernel<<<dim3(SEQ / 8, BNH), 256>>>(rsb, se);

    attn_fused<<<dim3(SEQ/128, 1, BNH), 512, attn_smem>>>();

    out_mma<<<dim3((SEQ*BAT)/128, DM/128), 256>>>(Wo, h);
    ln_kernel<<<SEQ*BAT, 256>>>(lns, lnb, out);
}